// round 6
// baseline (speedup 1.0000x reference)
#include <cuda_runtime.h>
#include <math.h>

#define LEAKY 0.01f
#define TPB 256

typedef unsigned long long ull;

__device__ __forceinline__ ull fma2(ull a, ull b, ull c) {
    ull d;
    asm("fma.rn.f32x2 %0, %1, %2, %3;" : "=l"(d) : "l"(a), "l"(b), "l"(c));
    return d;
}
__device__ __forceinline__ ull add2(ull a, ull b) {
    ull d;
    asm("add.rn.f32x2 %0, %1, %2;" : "=l"(d) : "l"(a), "l"(b));
    return d;
}
__device__ __forceinline__ ull pack2(float lo, float hi) {
    ull d;
    asm("mov.b64 %0, {%1, %2};" : "=l"(d) : "f"(lo), "f"(hi));
    return d;
}
__device__ __forceinline__ void unpack2(ull v, float& lo, float& hi) {
    asm("mov.b64 {%0, %1}, %2;" : "=f"(lo), "=f"(hi) : "l"(v));
}
// leaky(x) = max(x, 0.01*x): correct for both signs.
__device__ __forceinline__ ull leaky2(ull v) {
    float lo, hi;
    unpack2(v, lo, hi);
    lo = fmaxf(lo, LEAKY * lo);
    hi = fmaxf(hi, LEAKY * hi);
    return pack2(lo, hi);
}
__device__ __forceinline__ ull splat(float w) {
    unsigned u = __float_as_uint(w);
    return (ull)u | ((ull)u << 32);
}

// Bilinear gather for one point into f[0..2]
__device__ __forceinline__ void interp3(const float* __restrict__ grid,
                                        float px, float py, float* f) {
    float fx = px * 255.0f;
    float fy = py * 255.0f;
    int x0 = (int)fx, y0 = (int)fy;
    float xf = fx - (float)x0;
    float yf = fy - (float)y0;
    int x1 = min(x0 + 1, 255);
    int y1 = min(y0 + 1, 255);
    const float* tl = grid + (y0 * 256 + x0) * 3;
    const float* tr = grid + (y0 * 256 + x1) * 3;
    const float* bl = grid + (y1 * 256 + x0) * 3;
    const float* br = grid + (y1 * 256 + x1) * 3;
#pragma unroll
    for (int c = 0; c < 3; c++) {
        float top = (1.0f - xf) * __ldg(tl + c) + xf * __ldg(tr + c);
        float bot = (1.0f - xf) * __ldg(bl + c) + xf * __ldg(br + c);
        f[c] = (1.0f - yf) * top + yf * bot;
    }
}

__global__ __launch_bounds__(TPB) void mlp_fused_x2_kernel(
    const float* __restrict__ pos, const float* __restrict__ dir,
    const float* __restrict__ pos_grid, const float* __restrict__ dir_grid,
    const float* __restrict__ W1, const float* __restrict__ b1,
    const float* __restrict__ W2, const float* __restrict__ b2,
    const float* __restrict__ W3, const float* __restrict__ b3,
    float* __restrict__ out, int N)
{
    // All weights splatted (w,w) into shared: one LDS.64/128 -> packed operand.
    __shared__ __align__(16) ull sW2[4096];   // 32 KB
    __shared__ __align__(16) ull sW1[384];
    __shared__ ull sb1[64];
    __shared__ ull sb2[64];
    __shared__ ull sW3[64];
    __shared__ float sb3;

    const int t = threadIdx.x;
    for (int i = t; i < 4096; i += TPB) sW2[i] = splat(W2[i]);
    for (int i = t; i < 384;  i += TPB) sW1[i] = splat(W1[i]);
    if (t < 64) {
        sb1[t] = splat(b1[t]);
        sb2[t] = splat(b2[t]);
        sW3[t] = splat(W3[t]);
    }
    if (t == 0) sb3 = b3[0];
    __syncthreads();

    const int gid = blockIdx.x * TPB + t;       // handles points 2*gid, 2*gid+1
    if (2 * gid + 1 >= N) {
        if (2 * gid < N) {
            // odd tail (not hit for N=2^21, kept for safety): scalar fallback
            // handled by computing the pair with point duplicated.
        } else {
            return;
        }
    }

    // ---- Load 2 points, bilinear gathers ----
    const float4 pp = ((const float4*)pos)[gid];  // (pA.x pA.y pB.x pB.y)
    const float4 dd = ((const float4*)dir)[gid];

    float featA[6], featB[6];
    interp3(pos_grid, pp.x, pp.y, featA + 0);
    interp3(pos_grid, pp.z, pp.w, featB + 0);
    interp3(dir_grid, dd.x, dd.y, featA + 3);
    interp3(dir_grid, dd.z, dd.w, featB + 3);

    ull featP[6];
#pragma unroll
    for (int c = 0; c < 6; c++) featP[c] = pack2(featA[c], featB[c]);

    // ---- Layer 1: 6 -> 64 packed, leaky ----
    ull h1[64];
#pragma unroll
    for (int o = 0; o < 64; o++) {
        ull a = sb1[o];
#pragma unroll
        for (int i = 0; i < 6; i++)
            a = fma2(featP[i], sW1[o * 6 + i], a);
        h1[o] = leaky2(a);
    }

    // ---- Layer 2 (64->64, leaky) fused with Layer 3 (64->1), packed ----
    ull acc = pack2(sb3, sb3);
#pragma unroll 4
    for (int o = 0; o < 64; o++) {
        const ulonglong2* w2 = (const ulonglong2*)(sW2 + o * 64);
        ull a0 = sb2[o];
        ull a1 = 0ULL;  // packed (0,0)
#pragma unroll
        for (int j = 0; j < 32; j++) {
            ulonglong2 w = w2[j];           // weights 2j, 2j+1 (splatted)
            a0 = fma2(h1[2 * j + 0], w.x, a0);
            a1 = fma2(h1[2 * j + 1], w.y, a1);
        }
        ull a = leaky2(add2(a0, a1));
        acc = fma2(a, sW3[o], acc);
    }

    // ---- Sigmoid, store 2 outputs ----
    float xA, xB;
    unpack2(acc, xA, xB);
    float2 o2;
    o2.x = 1.0f / (1.0f + expf(-xA));
    o2.y = 1.0f / (1.0f + expf(-xB));
    ((float2*)out)[gid] = o2;
}

extern "C" void kernel_launch(void* const* d_in, const int* in_sizes, int n_in,
                              void* d_out, int out_size)
{
    const float* pos      = (const float*)d_in[0];
    const float* dir      = (const float*)d_in[1];
    const float* pos_grid = (const float*)d_in[2];
    const float* dir_grid = (const float*)d_in[3];
    const float* W1       = (const float*)d_in[4];
    const float* b1       = (const float*)d_in[5];
    const float* W2       = (const float*)d_in[6];
    const float* b2       = (const float*)d_in[7];
    const float* W3       = (const float*)d_in[8];
    const float* b3       = (const float*)d_in[9];
    float* out            = (float*)d_out;

    const int N = in_sizes[0] / 2;       // pos is (N, 2)
    const int pairs = N / 2;             // 2 points per thread
    const int blocks = (pairs + TPB - 1) / TPB;
    mlp_fused_x2_kernel<<<blocks, TPB>>>(pos, dir, pos_grid, dir_grid,
                                         W1, b1, W2, b2, W3, b3, out, N);
}

// round 9
// speedup vs baseline: 2.7324x; 2.7324x over previous
#include <cuda_runtime.h>
#include <cuda_bf16.h>
#include <cstdint>
#include <math.h>

#define TPB    128
#define LEAKY  0.01f

// ---- dynamic smem layout (offsets from 1024-aligned base) ----
// B (W2) tiles: 64 rows(n) x 128B(k), swizzled          8 KB each
#define B_HI_OFF 0
#define B_LO_OFF 8192
// A strips: per warp 32 rows x 128B hi + lo = 8 KB
#define A_OFF    16384
#define DYN_BYTES (49152 + 1024)

// ---------------- PTX helpers ----------------
__device__ __forceinline__ uint32_t smem_u32(const void* p) {
    uint32_t a;
    asm("{ .reg .u64 t; cvta.to.shared.u64 t, %1; cvt.u32.u64 %0, t; }" : "=r"(a) : "l"(p));
    return a;
}
__device__ __forceinline__ void ldsm_x4(uint32_t* r, uint32_t addr) {
    asm volatile("ldmatrix.sync.aligned.m8n8.x4.shared.b16 {%0,%1,%2,%3}, [%4];"
                 : "=r"(r[0]), "=r"(r[1]), "=r"(r[2]), "=r"(r[3]) : "r"(addr));
}
__device__ __forceinline__ void ldsm_x2(uint32_t* r, uint32_t addr) {
    asm volatile("ldmatrix.sync.aligned.m8n8.x2.shared.b16 {%0,%1}, [%2];"
                 : "=r"(r[0]), "=r"(r[1]) : "r"(addr));
}
__device__ __forceinline__ void mma_bf16(float* d, const uint32_t* a,
                                         uint32_t b0, uint32_t b1) {
    asm volatile("mma.sync.aligned.m16n8k16.row.col.f32.bf16.bf16.f32 "
                 "{%0,%1,%2,%3}, {%4,%5,%6,%7}, {%8,%9}, {%0,%1,%2,%3};"
                 : "+f"(d[0]), "+f"(d[1]), "+f"(d[2]), "+f"(d[3])
                 : "r"(a[0]), "r"(a[1]), "r"(a[2]), "r"(a[3]), "r"(b0), "r"(b1));
}

// bilinear gather for one point into f[0..2]
__device__ __forceinline__ void interp3(const float* __restrict__ grid,
                                        float px, float py, float* f) {
    float fx = px * 255.0f, fy = py * 255.0f;
    int x0 = (int)fx, y0 = (int)fy;
    float xf = fx - (float)x0, yf = fy - (float)y0;
    int x1 = min(x0 + 1, 255), y1 = min(y0 + 1, 255);
    const float* tl = grid + (y0 * 256 + x0) * 3;
    const float* tr = grid + (y0 * 256 + x1) * 3;
    const float* bl = grid + (y1 * 256 + x0) * 3;
    const float* br = grid + (y1 * 256 + x1) * 3;
#pragma unroll
    for (int c = 0; c < 3; c++) {
        float top = (1.0f - xf) * __ldg(tl + c) + xf * __ldg(tr + c);
        float bot = (1.0f - xf) * __ldg(bl + c) + xf * __ldg(br + c);
        f[c] = (1.0f - yf) * top + yf * bot;
    }
}

__device__ __forceinline__ void split_pair(float p0, float p1,
                                           uint32_t& hi, uint32_t& lo) {
    __nv_bfloat162 hp = __floats2bfloat162_rn(p0, p1);
    float r0 = p0 - __bfloat162float(hp.x);
    float r1 = p1 - __bfloat162float(hp.y);
    __nv_bfloat162 lp = __floats2bfloat162_rn(r0, r1);
    hi = *(uint32_t*)&hp;
    lo = *(uint32_t*)&lp;
}

__global__ __launch_bounds__(TPB, 4) void mlp_hmma_kernel(
    const float* __restrict__ pos, const float* __restrict__ dir,
    const float* __restrict__ pos_grid, const float* __restrict__ dir_grid,
    const float* __restrict__ W1, const float* __restrict__ b1,
    const float* __restrict__ W2, const float* __restrict__ b2,
    const float* __restrict__ W3, const float* __restrict__ b3,
    float* __restrict__ out, int N, int ntiles)
{
    extern __shared__ char dynsmem[];
    __shared__ __align__(16) float sW1t[384];   // transposed: [i][o]
    __shared__ __align__(16) float sB1[64];
    __shared__ __align__(16) float sB2[64];
    __shared__ __align__(16) float sW3[64];
    __shared__ float sb3;

    const uint32_t raw  = smem_u32(dynsmem);
    const uint32_t base = (raw + 1023u) & ~1023u;
    char* smem = dynsmem + (base - raw);

    const int t    = threadIdx.x;
    const int wid  = t >> 5;
    const int lane = t & 31;
    const int tg   = lane & 3;      // thread-in-group (cols)
    const int g    = lane >> 2;     // group (rows)

    // ---- one-time staging ----
    // W2 -> bf16 hi/lo, swizzled [n][k] rows of 128B
    for (int i = t; i < 4096; i += TPB) {
        float w = W2[i];
        __nv_bfloat16 h = __float2bfloat16(w);
        float r = w - __bfloat162float(h);
        __nv_bfloat16 l = __float2bfloat16(r);
        int n = i >> 6, k = i & 63;
        uint32_t off = (uint32_t)(n * 128) + (uint32_t)((k * 2) ^ ((n & 7) << 4));
        *(__nv_bfloat16*)(smem + B_HI_OFF + off) = h;
        *(__nv_bfloat16*)(smem + B_LO_OFF + off) = l;
    }
    for (int j = t; j < 384; j += TPB) {
        int o = j / 6, i = j % 6;
        sW1t[i * 64 + o] = W1[j];
    }
    if (t < 64) { sB1[t] = b1[t]; sB2[t] = b2[t]; sW3[t] = W3[t]; }
    if (t == 0) sb3 = b3[0];
    __syncthreads();

    const uint32_t aHi = base + A_OFF + wid * 8192;
    const uint32_t aLo = aHi + 4096;
    const uint32_t bHi = base + B_HI_OFF;
    const uint32_t bLo = base + B_LO_OFF;

    // precomputed per-lane ldmatrix address components
    const int rowA  = lane & 15;            // A: row within 16-row tile
    const int khA   = lane >> 4;            // A: k-half (0/1)
    const int rowB  = lane & 7;             // B: row within 8-row tile
    const int khB   = (lane >> 3) & 1;      // B: k-half

    const int warp_global = blockIdx.x * 4 + wid;
    const int warp_stride = gridDim.x * 4;

    for (int tile = warp_global; tile < ntiles; tile += warp_stride) {
        const int idx  = tile * 32 + lane;
        const bool live = (idx < N);

        // ---- interp + layer 1 (vectorized over o) ----
        float feat[6];
        if (live) {
            const float2 p = ((const float2*)pos)[idx];
            const float2 d = ((const float2*)dir)[idx];
            interp3(pos_grid, p.x, p.y, feat + 0);
            interp3(dir_grid, d.x, d.y, feat + 3);
        } else {
#pragma unroll
            for (int i = 0; i < 6; i++) feat[i] = 0.0f;
        }

        float4 h4[16];
        const float4* b14  = (const float4*)sB1;
        const float4* w1t4 = (const float4*)sW1t;
#pragma unroll
        for (int q = 0; q < 16; q++) h4[q] = b14[q];
#pragma unroll
        for (int i = 0; i < 6; i++) {
            const float f = feat[i];
#pragma unroll
            for (int q = 0; q < 16; q++) {
                float4 w = w1t4[i * 16 + q];
                h4[q].x = fmaf(f, w.x, h4[q].x);
                h4[q].y = fmaf(f, w.y, h4[q].y);
                h4[q].z = fmaf(f, w.z, h4[q].z);
                h4[q].w = fmaf(f, w.w, h4[q].w);
            }
        }
#pragma unroll
        for (int q = 0; q < 16; q++) {
            h4[q].x = fmaxf(h4[q].x, LEAKY * h4[q].x);
            h4[q].y = fmaxf(h4[q].y, LEAKY * h4[q].y);
            h4[q].z = fmaxf(h4[q].z, LEAKY * h4[q].z);
            h4[q].w = fmaxf(h4[q].w, LEAKY * h4[q].w);
        }

        __syncwarp();   // strip free for overwrite (prev iter's ldmatrix done)

        // ---- split to bf16 hi/lo, store row 'lane' (swizzled 16B chunks) ----
#pragma unroll
        for (int gc = 0; gc < 8; gc++) {
            float4 va = h4[2 * gc], vb = h4[2 * gc + 1];
            uint4 hw, lw;
            split_pair(va.x, va.y, hw.x, lw.x);
            split_pair(va.z, va.w, hw.y, lw.y);
            split_pair(vb.x, vb.y, hw.z, lw.z);
            split_pair(vb.z, vb.w, hw.w, lw.w);
            uint32_t off = (uint32_t)(lane * 128) + (uint32_t)((gc ^ (lane & 7)) << 4);
            *(uint4*)(smem + (aHi - base) + off) = hw;
            *(uint4*)(smem + (aLo - base) + off) = lw;
        }
        __syncwarp();

        // ---- A fragments: 2 M-tiles x 4 K-tiles ----
        uint32_t Ah[2][4][4], Al[2][4][4];
#pragma unroll
        for (int mt = 0; mt < 2; mt++) {
#pragma unroll
            for (int kt = 0; kt < 4; kt++) {
                int row = mt * 16 + rowA;
                uint32_t off = (uint32_t)(row * 128) +
                               (uint32_t)(((kt * 2 + khA) ^ (row & 7)) << 4);
                ldsm_x4(Ah[mt][kt], aHi + off);
                ldsm_x4(Al[mt][kt], aLo + off);
            }
        }

        // ---- GEMM + epilogue over 8 N-tiles ----
        float acc0 = 0.0f, acc1 = 0.0f, acc2 = 0.0f, acc3 = 0.0f;
#pragma unroll
        for (int n = 0; n < 8; n++) {
            float D0[4] = {0, 0, 0, 0};
            float D1[4] = {0, 0, 0, 0};
#pragma unroll
            for (int kt = 0; kt < 4; kt++) {
                int row = n * 8 + rowB;
                uint32_t off = (uint32_t)(row * 128) +
                               (uint32_t)(((kt * 2 + khB) ^ rowB) << 4);
                uint32_t bh[2], bl[2];
                ldsm_x2(bh, bHi + off);
                ldsm_x2(bl, bLo + off);
                mma_bf16(D0, Ah[0][kt], bh[0], bh[1]);
                mma_bf16(D0, Al[0][kt], bh[0], bh[1]);
                mma_bf16(D0, Ah[0][kt], bl[0], bl[1]);
                mma_bf16(D1, Ah[1][kt], bh[0], bh[1]);
                mma_bf16(D1, Al[1][kt], bh[0], bh[1]);
                mma_bf16(D1, Ah[1][kt], bl[0], bl[1]);
            }
            // epilogue for cols c0 = n*8 + tg*2, c0+1
            int c0 = n * 8 + tg * 2;
            float2 w3 = *(const float2*)&sW3[c0];
            float2 bb = *(const float2*)&sB2[c0];
            float v;
            v = D0[0] + bb.x; v = fmaxf(v, LEAKY * v); acc0 = fmaf(v, w3.x, acc0);
            v = D0[1] + bb.y; v = fmaxf(v, LEAKY * v); acc0 = fmaf(v, w3.y, acc0);
            v = D0[2] + bb.x; v = fmaxf(v, LEAKY * v); acc1 = fmaf(v, w3.x, acc1);
            v = D0[3] + bb.y; v = fmaxf(v, LEAKY * v); acc1 = fmaf(v, w3.y, acc1);
            v = D1[0] + bb.x; v = fmaxf(v, LEAKY * v); acc2 = fmaf(v, w3.x, acc2);
            v = D1[1] + bb.y; v = fmaxf(v, LEAKY * v); acc2 = fmaf(v, w3.y, acc2);
            v = D1[2] + bb.x; v = fmaxf(v, LEAKY * v); acc3 = fmaf(v, w3.x, acc3);
            v = D1[3] + bb.y; v = fmaxf(v, LEAKY * v); acc3 = fmaf(v, w3.y, acc3);
        }

        // ---- reduce over the 4 lanes sharing each row group ----
        acc0 += __shfl_xor_sync(0xFFFFFFFF, acc0, 1);
        acc0 += __shfl_xor_sync(0xFFFFFFFF, acc0, 2);
        acc1 += __shfl_xor_sync(0xFFFFFFFF, acc1, 1);
        acc1 += __shfl_xor_sync(0xFFFFFFFF, acc1, 2);
        acc2 += __shfl_xor_sync(0xFFFFFFFF, acc2, 1);
        acc2 += __shfl_xor_sync(0xFFFFFFFF, acc2, 2);
        acc3 += __shfl_xor_sync(0xFFFFFFFF, acc3, 1);
        acc3 += __shfl_xor_sync(0xFFFFFFFF, acc3, 2);

        if (tg == 0) {
            const int rbase = tile * 32 + g;
            float r0 = acc0 + sb3, r1 = acc1 + sb3, r2 = acc2 + sb3, r3 = acc3 + sb3;
            if (rbase      < N) out[rbase]      = 1.0f / (1.0f + expf(-r0));
            if (rbase + 8  < N) out[rbase + 8]  = 1.0f / (1.0f + expf(-r1));
            if (rbase + 16 < N) out[rbase + 16] = 1.0f / (1.0f + expf(-r2));
            if (rbase + 24 < N) out[rbase + 24] = 1.0f / (1.0f + expf(-r3));
        }
    }
}

extern "C" void kernel_launch(void* const* d_in, const int* in_sizes, int n_in,
                              void* d_out, int out_size)
{
    const float* pos      = (const float*)d_in[0];
    const float* dir      = (const float*)d_in[1];
    const float* pos_grid = (const float*)d_in[2];
    const float* dir_grid = (const float*)d_in[3];
    const float* W1       = (const float*)d_in[4];
    const float* b1       = (const float*)d_in[5];
    const float* W2       = (const float*)d_in[6];
    const float* b2       = (const float*)d_in[7];
    const float* W3       = (const float*)d_in[8];
    const float* b3       = (const float*)d_in[9];
    float* out            = (float*)d_out;

    const int N = in_sizes[0] / 2;             // pos is (N, 2)
    const int ntiles = (N + 31) / 32;          // 32 points per warp-tile

    cudaFuncSetAttribute(mlp_hmma_kernel,
                         cudaFuncAttributeMaxDynamicSharedMemorySize, DYN_BYTES);

    int grid = 608;                            // 152 SMs x 4 CTAs
    if (grid * 4 > ntiles) grid = (ntiles + 3) / 4;
    mlp_hmma_kernel<<<grid, TPB, DYN_BYTES>>>(pos, dir, pos_grid, dir_grid,
                                              W1, b1, W2, b2, W3, b3,
                                              out, N, ntiles);
}

// round 10
// speedup vs baseline: 2.8238x; 1.0334x over previous
#include <cuda_runtime.h>
#include <cuda_bf16.h>
#include <cstdint>
#include <math.h>

#define TPB    128
#define LEAKY  0.01f

// ---- dynamic smem layout (offsets from 1024-aligned base) ----
// B (W2) tiles: 64 rows(n) x 128B(k), swizzled          8 KB each
#define B_HI_OFF 0
#define B_LO_OFF 8192
// A strips: per warp 32 rows x 128B hi + lo = 8 KB
#define A_OFF    16384
#define DYN_BYTES (49152 + 1024)

// ---------------- PTX helpers ----------------
__device__ __forceinline__ uint32_t smem_u32(const void* p) {
    uint32_t a;
    asm("{ .reg .u64 t; cvta.to.shared.u64 t, %1; cvt.u32.u64 %0, t; }" : "=r"(a) : "l"(p));
    return a;
}
__device__ __forceinline__ void ldsm_x4(uint32_t* r, uint32_t addr) {
    asm volatile("ldmatrix.sync.aligned.m8n8.x4.shared.b16 {%0,%1,%2,%3}, [%4];"
                 : "=r"(r[0]), "=r"(r[1]), "=r"(r[2]), "=r"(r[3]) : "r"(addr));
}
__device__ __forceinline__ void mma_bf16(float* d, const uint32_t* a,
                                         uint32_t b0, uint32_t b1) {
    asm volatile("mma.sync.aligned.m16n8k16.row.col.f32.bf16.bf16.f32 "
                 "{%0,%1,%2,%3}, {%4,%5,%6,%7}, {%8,%9}, {%0,%1,%2,%3};"
                 : "+f"(d[0]), "+f"(d[1]), "+f"(d[2]), "+f"(d[3])
                 : "r"(a[0]), "r"(a[1]), "r"(a[2]), "r"(a[3]), "r"(b0), "r"(b1));
}

// bilinear gather for one point into f[0..2]
__device__ __forceinline__ void interp3(const float* __restrict__ grid,
                                        float px, float py, float* f) {
    float fx = px * 255.0f, fy = py * 255.0f;
    int x0 = (int)fx, y0 = (int)fy;
    float xf = fx - (float)x0, yf = fy - (float)y0;
    int x1 = min(x0 + 1, 255), y1 = min(y0 + 1, 255);
    const float* tl = grid + (y0 * 256 + x0) * 3;
    const float* tr = grid + (y0 * 256 + x1) * 3;
    const float* bl = grid + (y1 * 256 + x0) * 3;
    const float* br = grid + (y1 * 256 + x1) * 3;
#pragma unroll
    for (int c = 0; c < 3; c++) {
        float top = (1.0f - xf) * __ldg(tl + c) + xf * __ldg(tr + c);
        float bot = (1.0f - xf) * __ldg(bl + c) + xf * __ldg(br + c);
        f[c] = (1.0f - yf) * top + yf * bot;
    }
}

__device__ __forceinline__ void split_pair(float p0, float p1,
                                           uint32_t& hi, uint32_t& lo) {
    __nv_bfloat162 hp = __floats2bfloat162_rn(p0, p1);
    float r0 = p0 - __bfloat162float(hp.x);
    float r1 = p1 - __bfloat162float(hp.y);
    __nv_bfloat162 lp = __floats2bfloat162_rn(r0, r1);
    hi = *(uint32_t*)&hp;
    lo = *(uint32_t*)&lp;
}

__global__ __launch_bounds__(TPB, 4) void mlp_hmma_kernel(
    const float* __restrict__ pos, const float* __restrict__ dir,
    const float* __restrict__ pos_grid, const float* __restrict__ dir_grid,
    const float* __restrict__ W1, const float* __restrict__ b1,
    const float* __restrict__ W2, const float* __restrict__ b2,
    const float* __restrict__ W3, const float* __restrict__ b3,
    float* __restrict__ out, int N, int ntiles)
{
    extern __shared__ char dynsmem[];
    __shared__ __align__(16) float sW1t[384];   // transposed: [i][o]
    __shared__ __align__(16) float sB1[64];
    __shared__ __align__(16) float sB2[64];
    __shared__ __align__(16) float sW3[64];
    __shared__ float sb3;

    const uint32_t raw  = smem_u32(dynsmem);
    const uint32_t base = (raw + 1023u) & ~1023u;
    char* smem = dynsmem + (base - raw);

    const int t    = threadIdx.x;
    const int wid  = t >> 5;
    const int lane = t & 31;
    const int tg   = lane & 3;      // thread-in-group (cols)
    const int g    = lane >> 2;     // group (rows)

    // ---- one-time staging ----
    // W2 -> bf16 hi/lo, swizzled [n][k] rows of 128B
    for (int i = t; i < 4096; i += TPB) {
        float w = W2[i];
        __nv_bfloat16 h = __float2bfloat16(w);
        float r = w - __bfloat162float(h);
        __nv_bfloat16 l = __float2bfloat16(r);
        int n = i >> 6, k = i & 63;
        uint32_t off = (uint32_t)(n * 128) + (uint32_t)((k * 2) ^ ((n & 7) << 4));
        *(__nv_bfloat16*)(smem + B_HI_OFF + off) = h;
        *(__nv_bfloat16*)(smem + B_LO_OFF + off) = l;
    }
    for (int j = t; j < 384; j += TPB) {
        int o = j / 6, i = j % 6;
        sW1t[i * 64 + o] = W1[j];
    }
    if (t < 64) { sB1[t] = b1[t]; sB2[t] = b2[t]; sW3[t] = W3[t]; }
    if (t == 0) sb3 = b3[0];
    __syncthreads();

    const uint32_t aHi = base + A_OFF + wid * 8192;
    const uint32_t aLo = aHi + 4096;
    const uint32_t bHi = base + B_HI_OFF;
    const uint32_t bLo = base + B_LO_OFF;

    // per-lane ldmatrix address components
    const int rowA  = lane & 15;            // A: row within 16-row tile
    const int khA   = lane >> 4;            // A: k-half (0/1)
    // B x4 packing: lanes 0-7 -> (n0,kh0), 8-15 -> (n0,kh1),
    //               16-23 -> (n1,kh0), 24-31 -> (n1,kh1)
    const int matB  = lane >> 3;            // 0..3
    const int nSub  = matB >> 1;            // n-tile within pair
    const int khB   = matB & 1;             // k-half
    const int rowB7 = lane & 7;

    const int warp_global = blockIdx.x * 4 + wid;
    const int warp_stride = gridDim.x * 4;

    for (int tile = warp_global; tile < ntiles; tile += warp_stride) {
        const int idx  = tile * 32 + lane;
        const bool live = (idx < N);

        // ---- interp + layer 1 (vectorized over o) ----
        float feat[6];
        if (live) {
            const float2 p = ((const float2*)pos)[idx];
            const float2 d = ((const float2*)dir)[idx];
            interp3(pos_grid, p.x, p.y, feat + 0);
            interp3(dir_grid, d.x, d.y, feat + 3);
        } else {
#pragma unroll
            for (int i = 0; i < 6; i++) feat[i] = 0.0f;
        }

        float4 h4[16];
        const float4* b14  = (const float4*)sB1;
        const float4* w1t4 = (const float4*)sW1t;
#pragma unroll
        for (int q = 0; q < 16; q++) h4[q] = b14[q];
#pragma unroll
        for (int i = 0; i < 6; i++) {
            const float f = feat[i];
#pragma unroll
            for (int q = 0; q < 16; q++) {
                float4 w = w1t4[i * 16 + q];
                h4[q].x = fmaf(f, w.x, h4[q].x);
                h4[q].y = fmaf(f, w.y, h4[q].y);
                h4[q].z = fmaf(f, w.z, h4[q].z);
                h4[q].w = fmaf(f, w.w, h4[q].w);
            }
        }
#pragma unroll
        for (int q = 0; q < 16; q++) {
            h4[q].x = fmaxf(h4[q].x, LEAKY * h4[q].x);
            h4[q].y = fmaxf(h4[q].y, LEAKY * h4[q].y);
            h4[q].z = fmaxf(h4[q].z, LEAKY * h4[q].z);
            h4[q].w = fmaxf(h4[q].w, LEAKY * h4[q].w);
        }

        __syncwarp();   // strip free for overwrite (prev iter's ldmatrix done)

        // ---- split to bf16 hi/lo, store row 'lane' (swizzled 16B chunks) ----
#pragma unroll
        for (int gc = 0; gc < 8; gc++) {
            float4 va = h4[2 * gc], vb = h4[2 * gc + 1];
            uint4 hw, lw;
            split_pair(va.x, va.y, hw.x, lw.x);
            split_pair(va.z, va.w, hw.y, lw.y);
            split_pair(vb.x, vb.y, hw.z, lw.z);
            split_pair(vb.z, vb.w, hw.w, lw.w);
            uint32_t off = (uint32_t)(lane * 128) + (uint32_t)((gc ^ (lane & 7)) << 4);
            *(uint4*)(smem + (aHi - base) + off) = hw;
            *(uint4*)(smem + (aLo - base) + off) = lw;
        }
        __syncwarp();

        // ---- A fragments: 2 M-tiles x 4 K-tiles ----
        uint32_t Ah[2][4][4], Al[2][4][4];
#pragma unroll
        for (int mt = 0; mt < 2; mt++) {
#pragma unroll
            for (int kt = 0; kt < 4; kt++) {
                int row = mt * 16 + rowA;
                uint32_t off = (uint32_t)(row * 128) +
                               (uint32_t)(((kt * 2 + khA) ^ (row & 7)) << 4);
                ldsm_x4(Ah[mt][kt], aHi + off);
                ldsm_x4(Al[mt][kt], aLo + off);
            }
        }

        // ---- GEMM + epilogue over 4 n-pairs (x4 B loads) ----
        float acc0 = 0.0f, acc1 = 0.0f, acc2 = 0.0f, acc3 = 0.0f;
#pragma unroll
        for (int np = 0; np < 4; np++) {
            float D0a[4] = {0, 0, 0, 0};
            float D0b[4] = {0, 0, 0, 0};
            float D1a[4] = {0, 0, 0, 0};
            float D1b[4] = {0, 0, 0, 0};
            const uint32_t rOff = (uint32_t)(((np * 2 + nSub) * 8 + rowB7) * 128);
#pragma unroll
            for (int kt = 0; kt < 4; kt++) {
                uint32_t off = rOff + (uint32_t)(((kt * 2 + khB) ^ rowB7) << 4);
                uint32_t bh[4], bl[4];
                ldsm_x4(bh, bHi + off);
                ldsm_x4(bl, bLo + off);
                mma_bf16(D0a, Ah[0][kt], bh[0], bh[1]);
                mma_bf16(D0a, Al[0][kt], bh[0], bh[1]);
                mma_bf16(D0a, Ah[0][kt], bl[0], bl[1]);
                mma_bf16(D0b, Ah[0][kt], bh[2], bh[3]);
                mma_bf16(D0b, Al[0][kt], bh[2], bh[3]);
                mma_bf16(D0b, Ah[0][kt], bl[2], bl[3]);
                mma_bf16(D1a, Ah[1][kt], bh[0], bh[1]);
                mma_bf16(D1a, Al[1][kt], bh[0], bh[1]);
                mma_bf16(D1a, Ah[1][kt], bl[0], bl[1]);
                mma_bf16(D1b, Ah[1][kt], bh[2], bh[3]);
                mma_bf16(D1b, Al[1][kt], bh[2], bh[3]);
                mma_bf16(D1b, Ah[1][kt], bl[2], bl[3]);
            }
            // epilogue: n-tiles np*2 (a) and np*2+1 (b)
#pragma unroll
            for (int s = 0; s < 2; s++) {
                const float* D0 = s ? D0b : D0a;
                const float* D1 = s ? D1b : D1a;
                int c0 = (np * 2 + s) * 8 + tg * 2;
                float2 w3 = *(const float2*)&sW3[c0];
                float2 bb = *(const float2*)&sB2[c0];
                float v;
                v = D0[0] + bb.x; v = fmaxf(v, LEAKY * v); acc0 = fmaf(v, w3.x, acc0);
                v = D0[1] + bb.y; v = fmaxf(v, LEAKY * v); acc0 = fmaf(v, w3.y, acc0);
                v = D0[2] + bb.x; v = fmaxf(v, LEAKY * v); acc1 = fmaf(v, w3.x, acc1);
                v = D0[3] + bb.y; v = fmaxf(v, LEAKY * v); acc1 = fmaf(v, w3.y, acc1);
                v = D1[0] + bb.x; v = fmaxf(v, LEAKY * v); acc2 = fmaf(v, w3.x, acc2);
                v = D1[1] + bb.y; v = fmaxf(v, LEAKY * v); acc2 = fmaf(v, w3.y, acc2);
                v = D1[2] + bb.x; v = fmaxf(v, LEAKY * v); acc3 = fmaf(v, w3.x, acc3);
                v = D1[3] + bb.y; v = fmaxf(v, LEAKY * v); acc3 = fmaf(v, w3.y, acc3);
            }
        }

        // ---- reduce over the 4 lanes sharing each row group ----
        acc0 += __shfl_xor_sync(0xFFFFFFFF, acc0, 1);
        acc0 += __shfl_xor_sync(0xFFFFFFFF, acc0, 2);
        acc1 += __shfl_xor_sync(0xFFFFFFFF, acc1, 1);
        acc1 += __shfl_xor_sync(0xFFFFFFFF, acc1, 2);
        acc2 += __shfl_xor_sync(0xFFFFFFFF, acc2, 1);
        acc2 += __shfl_xor_sync(0xFFFFFFFF, acc2, 2);
        acc3 += __shfl_xor_sync(0xFFFFFFFF, acc3, 1);
        acc3 += __shfl_xor_sync(0xFFFFFFFF, acc3, 2);

        if (tg == 0) {
            const int rbase = tile * 32 + g;
            float r0 = acc0 + sb3, r1 = acc1 + sb3, r2 = acc2 + sb3, r3 = acc3 + sb3;
            if (rbase      < N) out[rbase]      = 1.0f / (1.0f + expf(-r0));
            if (rbase + 8  < N) out[rbase + 8]  = 1.0f / (1.0f + expf(-r1));
            if (rbase + 16 < N) out[rbase + 16] = 1.0f / (1.0f + expf(-r2));
            if (rbase + 24 < N) out[rbase + 24] = 1.0f / (1.0f + expf(-r3));
        }
    }
}

extern "C" void kernel_launch(void* const* d_in, const int* in_sizes, int n_in,
                              void* d_out, int out_size)
{
    const float* pos      = (const float*)d_in[0];
    const float* dir      = (const float*)d_in[1];
    const float* pos_grid = (const float*)d_in[2];
    const float* dir_grid = (const float*)d_in[3];
    const float* W1       = (const float*)d_in[4];
    const float* b1       = (const float*)d_in[5];
    const float* W2       = (const float*)d_in[6];
    const float* b2       = (const float*)d_in[7];
    const float* W3       = (const float*)d_in[8];
    const float* b3       = (const float*)d_in[9];
    float* out            = (float*)d_out;

    const int N = in_sizes[0] / 2;             // pos is (N, 2)
    const int ntiles = (N + 31) / 32;          // 32 points per warp-tile

    cudaFuncSetAttribute(mlp_hmma_kernel,
                         cudaFuncAttributeMaxDynamicSharedMemorySize, DYN_BYTES);

    int grid = 608;                            // 152 SMs x 4 CTAs
    if (grid * 4 > ntiles) grid = (ntiles + 3) / 4;
    mlp_hmma_kernel<<<grid, TPB, DYN_BYTES>>>(pos, dir, pos_grid, dir_grid,
                                              W1, b1, W2, b2, W3, b3,
                                              out, N, ntiles);
}

// round 11
// speedup vs baseline: 3.5506x; 1.2574x over previous
#include <cuda_runtime.h>
#include <cuda_fp16.h>
#include <cstdint>
#include <math.h>

#define TPB    128
#define LEAKY  0.01f

// ---- dynamic smem layout (offsets from 1024-aligned base) ----
// B (W2) tiles: 64 rows(n) x 128B(k) fp16, swizzled   8 KB each (hi, lo)
#define B_HI_OFF 0
#define B_LO_OFF 8192
// A strips: per warp 32 rows x 128B (64 fp16) = 4 KB
#define A_OFF    16384
#define DYN_BYTES (32768 + 1024)

// ---------------- PTX helpers ----------------
__device__ __forceinline__ uint32_t smem_u32(const void* p) {
    uint32_t a;
    asm("{ .reg .u64 t; cvta.to.shared.u64 t, %1; cvt.u32.u64 %0, t; }" : "=r"(a) : "l"(p));
    return a;
}
__device__ __forceinline__ void ldsm_x4(uint32_t* r, uint32_t addr) {
    asm volatile("ldmatrix.sync.aligned.m8n8.x4.shared.b16 {%0,%1,%2,%3}, [%4];"
                 : "=r"(r[0]), "=r"(r[1]), "=r"(r[2]), "=r"(r[3]) : "r"(addr));
}
__device__ __forceinline__ void mma_f16(float* d, const uint32_t* a,
                                        uint32_t b0, uint32_t b1) {
    asm volatile("mma.sync.aligned.m16n8k16.row.col.f32.f16.f16.f32 "
                 "{%0,%1,%2,%3}, {%4,%5,%6,%7}, {%8,%9}, {%0,%1,%2,%3};"
                 : "+f"(d[0]), "+f"(d[1]), "+f"(d[2]), "+f"(d[3])
                 : "r"(a[0]), "r"(a[1]), "r"(a[2]), "r"(a[3]), "r"(b0), "r"(b1));
}

// bilinear gather for one point into f[0..2]
__device__ __forceinline__ void interp3(const float* __restrict__ grid,
                                        float px, float py, float* f) {
    float fx = px * 255.0f, fy = py * 255.0f;
    int x0 = (int)fx, y0 = (int)fy;
    float xf = fx - (float)x0, yf = fy - (float)y0;
    int x1 = min(x0 + 1, 255), y1 = min(y0 + 1, 255);
    const float* tl = grid + (y0 * 256 + x0) * 3;
    const float* tr = grid + (y0 * 256 + x1) * 3;
    const float* bl = grid + (y1 * 256 + x0) * 3;
    const float* br = grid + (y1 * 256 + x1) * 3;
#pragma unroll
    for (int c = 0; c < 3; c++) {
        float top = (1.0f - xf) * __ldg(tl + c) + xf * __ldg(tr + c);
        float bot = (1.0f - xf) * __ldg(bl + c) + xf * __ldg(br + c);
        f[c] = (1.0f - yf) * top + yf * bot;
    }
}

__global__ __launch_bounds__(TPB, 5) void mlp_hmma_kernel(
    const float* __restrict__ pos, const float* __restrict__ dir,
    const float* __restrict__ pos_grid, const float* __restrict__ dir_grid,
    const float* __restrict__ W1, const float* __restrict__ b1,
    const float* __restrict__ W2, const float* __restrict__ b2,
    const float* __restrict__ W3, const float* __restrict__ b3,
    float* __restrict__ out, int N, int ntiles)
{
    extern __shared__ char dynsmem[];
    __shared__ __align__(16) float sW1t[384];   // transposed: [i][o]
    __shared__ __align__(16) float sB1[64];
    __shared__ __align__(16) float sB2[64];
    __shared__ __align__(16) float sW3[64];
    __shared__ float sb3;

    const uint32_t raw  = smem_u32(dynsmem);
    const uint32_t base = (raw + 1023u) & ~1023u;
    char* smem = dynsmem + (base - raw);

    const int t    = threadIdx.x;
    const int wid  = t >> 5;
    const int lane = t & 31;
    const int tg   = lane & 3;      // thread-in-group (cols)
    const int g    = lane >> 2;     // group (rows)

    // ---- one-time staging: W2 -> fp16 hi/lo, swizzled [n][k] 128B rows ----
    for (int i = t; i < 4096; i += TPB) {
        float w = W2[i];
        __half h = __float2half_rn(w);
        __half l = __float2half_rn(w - __half2float(h));
        int n = i >> 6, k = i & 63;
        uint32_t off = (uint32_t)(n * 128) + (uint32_t)((k * 2) ^ ((n & 7) << 4));
        *(__half*)(smem + B_HI_OFF + off) = h;
        *(__half*)(smem + B_LO_OFF + off) = l;
    }
    for (int j = t; j < 384; j += TPB) {
        int o = j / 6, i = j % 6;
        sW1t[i * 64 + o] = W1[j];
    }
    if (t < 64) { sB1[t] = b1[t]; sB2[t] = b2[t]; sW3[t] = W3[t]; }
    if (t == 0) sb3 = b3[0];
    __syncthreads();

    const uint32_t aStrip = base + A_OFF + wid * 4096;
    const uint32_t bHi = base + B_HI_OFF;
    const uint32_t bLo = base + B_LO_OFF;

    // per-lane ldmatrix address components
    const int rowA  = lane & 15;            // A: row within 16-row tile
    const int khA   = lane >> 4;            // A: k-half (0/1)
    // B x4 packing: lanes 0-7 -> (n0,kh0), 8-15 -> (n0,kh1),
    //               16-23 -> (n1,kh0), 24-31 -> (n1,kh1)
    const int matB  = lane >> 3;
    const int nSub  = matB >> 1;
    const int khB   = matB & 1;
    const int rowB7 = lane & 7;

    const int warp_global = blockIdx.x * 4 + wid;
    const int warp_stride = gridDim.x * 4;

    for (int tile = warp_global; tile < ntiles; tile += warp_stride) {
        const int idx  = tile * 32 + lane;
        const bool live = (idx < N);

        // ---- interp ----
        float feat[6];
        if (live) {
            const float2 p = ((const float2*)pos)[idx];
            const float2 d = ((const float2*)dir)[idx];
            interp3(pos_grid, p.x, p.y, feat + 0);
            interp3(dir_grid, d.x, d.y, feat + 3);
        } else {
#pragma unroll
            for (int i = 0; i < 6; i++) feat[i] = 0.0f;
        }

        __syncwarp();   // strip free for overwrite (prev iter's ldmatrix done)

        // ---- layer 1 in two 32-output chunks; fp16 pack; store strip ----
        const float4* b14  = (const float4*)sB1;
        const float4* w1t4 = (const float4*)sW1t;
#pragma unroll
        for (int c = 0; c < 2; c++) {
            float4 h4[8];
#pragma unroll
            for (int q = 0; q < 8; q++) h4[q] = b14[c * 8 + q];
#pragma unroll
            for (int i = 0; i < 6; i++) {
                const float f = feat[i];
#pragma unroll
                for (int q = 0; q < 8; q++) {
                    float4 w = w1t4[i * 16 + c * 8 + q];
                    h4[q].x = fmaf(f, w.x, h4[q].x);
                    h4[q].y = fmaf(f, w.y, h4[q].y);
                    h4[q].z = fmaf(f, w.z, h4[q].z);
                    h4[q].w = fmaf(f, w.w, h4[q].w);
                }
            }
            // leaky + cvt fp16 + store (16B chunks, swizzled within 128B row)
#pragma unroll
            for (int j = 0; j < 4; j++) {
                float4 va = h4[2 * j], vb = h4[2 * j + 1];
                va.x = fmaxf(va.x, LEAKY * va.x);
                va.y = fmaxf(va.y, LEAKY * va.y);
                va.z = fmaxf(va.z, LEAKY * va.z);
                va.w = fmaxf(va.w, LEAKY * va.w);
                vb.x = fmaxf(vb.x, LEAKY * vb.x);
                vb.y = fmaxf(vb.y, LEAKY * vb.y);
                vb.z = fmaxf(vb.z, LEAKY * vb.z);
                vb.w = fmaxf(vb.w, LEAKY * vb.w);
                __half2 p0 = __floats2half2_rn(va.x, va.y);
                __half2 p1 = __floats2half2_rn(va.z, va.w);
                __half2 p2 = __floats2half2_rn(vb.x, vb.y);
                __half2 p3 = __floats2half2_rn(vb.z, vb.w);
                uint4 pk = make_uint4(*(uint32_t*)&p0, *(uint32_t*)&p1,
                                      *(uint32_t*)&p2, *(uint32_t*)&p3);
                int gc = c * 4 + j;
                uint32_t off = (uint32_t)(lane * 128) +
                               (uint32_t)((gc ^ (lane & 7)) << 4);
                *(uint4*)(smem + (aStrip - base) + off) = pk;
            }
        }
        __syncwarp();

        // ---- A fragments: 2 M-tiles x 4 K-tiles (single precision term) ----
        uint32_t Ah[2][4][4];
#pragma unroll
        for (int mt = 0; mt < 2; mt++) {
#pragma unroll
            for (int kt = 0; kt < 4; kt++) {
                int row = mt * 16 + rowA;
                uint32_t off = (uint32_t)(row * 128) +
                               (uint32_t)(((kt * 2 + khA) ^ (row & 7)) << 4);
                ldsm_x4(Ah[mt][kt], aStrip + off);
            }
        }

        // ---- GEMM + epilogue over 4 n-pairs: D = A*Bh + A*Bl ----
        float acc0 = 0.0f, acc1 = 0.0f, acc2 = 0.0f, acc3 = 0.0f;
#pragma unroll
        for (int np = 0; np < 4; np++) {
            float D0a[4] = {0, 0, 0, 0};
            float D0b[4] = {0, 0, 0, 0};
            float D1a[4] = {0, 0, 0, 0};
            float D1b[4] = {0, 0, 0, 0};
            const uint32_t rOff = (uint32_t)(((np * 2 + nSub) * 8 + rowB7) * 128);
#pragma unroll
            for (int kt = 0; kt < 4; kt++) {
                uint32_t off = rOff + (uint32_t)(((kt * 2 + khB) ^ rowB7) << 4);
                uint32_t bh[4], bl[4];
                ldsm_x4(bh, bHi + off);
                ldsm_x4(bl, bLo + off);
                mma_f16(D0a, Ah[0][kt], bh[0], bh[1]);
                mma_f16(D0a, Ah[0][kt], bl[0], bl[1]);
                mma_f16(D0b, Ah[0][kt], bh[2], bh[3]);
                mma_f16(D0b, Ah[0][kt], bl[2], bl[3]);
                mma_f16(D1a, Ah[1][kt], bh[0], bh[1]);
                mma_f16(D1a, Ah[1][kt], bl[0], bl[1]);
                mma_f16(D1b, Ah[1][kt], bh[2], bh[3]);
                mma_f16(D1b, Ah[1][kt], bl[2], bl[3]);
            }
            // epilogue: n-tiles np*2 (a) and np*2+1 (b)
#pragma unroll
            for (int s = 0; s < 2; s++) {
                const float* D0 = s ? D0b : D0a;
                const float* D1 = s ? D1b : D1a;
                int c0 = (np * 2 + s) * 8 + tg * 2;
                float2 w3 = *(const float2*)&sW3[c0];
                float2 bb = *(const float2*)&sB2[c0];
                float v;
                v = D0[0] + bb.x; v = fmaxf(v, LEAKY * v); acc0 = fmaf(v, w3.x, acc0);
                v = D0[1] + bb.y; v = fmaxf(v, LEAKY * v); acc0 = fmaf(v, w3.y, acc0);
                v = D0[2] + bb.x; v = fmaxf(v, LEAKY * v); acc1 = fmaf(v, w3.x, acc1);
                v = D0[3] + bb.y; v = fmaxf(v, LEAKY * v); acc1 = fmaf(v, w3.y, acc1);
                v = D1[0] + bb.x; v = fmaxf(v, LEAKY * v); acc2 = fmaf(v, w3.x, acc2);
                v = D1[1] + bb.y; v = fmaxf(v, LEAKY * v); acc2 = fmaf(v, w3.y, acc2);
                v = D1[2] + bb.x; v = fmaxf(v, LEAKY * v); acc3 = fmaf(v, w3.x, acc3);
                v = D1[3] + bb.y; v = fmaxf(v, LEAKY * v); acc3 = fmaf(v, w3.y, acc3);
            }
        }

        // ---- reduce over the 4 lanes sharing each row group ----
        acc0 += __shfl_xor_sync(0xFFFFFFFF, acc0, 1);
        acc0 += __shfl_xor_sync(0xFFFFFFFF, acc0, 2);
        acc1 += __shfl_xor_sync(0xFFFFFFFF, acc1, 1);
        acc1 += __shfl_xor_sync(0xFFFFFFFF, acc1, 2);
        acc2 += __shfl_xor_sync(0xFFFFFFFF, acc2, 1);
        acc2 += __shfl_xor_sync(0xFFFFFFFF, acc2, 2);
        acc3 += __shfl_xor_sync(0xFFFFFFFF, acc3, 1);
        acc3 += __shfl_xor_sync(0xFFFFFFFF, acc3, 2);

        if (tg == 0) {
            const int rbase = tile * 32 + g;
            float r0 = acc0 + sb3, r1 = acc1 + sb3, r2 = acc2 + sb3, r3 = acc3 + sb3;
            if (rbase      < N) out[rbase]      = 1.0f / (1.0f + __expf(-r0));
            if (rbase + 8  < N) out[rbase + 8]  = 1.0f / (1.0f + __expf(-r1));
            if (rbase + 16 < N) out[rbase + 16] = 1.0f / (1.0f + __expf(-r2));
            if (rbase + 24 < N) out[rbase + 24] = 1.0f / (1.0f + __expf(-r3));
        }
    }
}

extern "C" void kernel_launch(void* const* d_in, const int* in_sizes, int n_in,
                              void* d_out, int out_size)
{
    const float* pos      = (const float*)d_in[0];
    const float* dir      = (const float*)d_in[1];
    const float* pos_grid = (const float*)d_in[2];
    const float* dir_grid = (const float*)d_in[3];
    const float* W1       = (const float*)d_in[4];
    const float* b1       = (const float*)d_in[5];
    const float* W2       = (const float*)d_in[6];
    const float* b2       = (const float*)d_in[7];
    const float* W3       = (const float*)d_in[8];
    const float* b3       = (const float*)d_in[9];
    float* out            = (float*)d_out;

    const int N = in_sizes[0] / 2;             // pos is (N, 2)
    const int ntiles = (N + 31) / 32;          // 32 points per warp-tile

    cudaFuncSetAttribute(mlp_hmma_kernel,
                         cudaFuncAttributeMaxDynamicSharedMemorySize, DYN_BYTES);

    int grid = 760;                            // 152 SMs x 5 CTAs
    if (grid * 4 > ntiles) grid = (ntiles + 3) / 4;
    mlp_hmma_kernel<<<grid, TPB, DYN_BYTES>>>(pos, dir, pos_grid, dir_grid,
                                              W1, b1, W2, b2, W3, b3,
                                              out, N, ntiles);
}

// round 12
// speedup vs baseline: 4.6479x; 1.3091x over previous
#include <cuda_runtime.h>
#include <cuda_fp16.h>
#include <cstdint>
#include <math.h>

#define TPB    128
#define LEAKY  0.01f

// ---- dynamic smem layout (offsets from 1024-aligned base) ----
#define B2_OFF   0                   // 8 KB: W2 fp16 [n=64][k=64], swizzled 128B rows
#define W1F_OFF  8192                // 2 KB: W1 fp16 [n=64][k=8]; hi @+0, lo @+1024
#define A_OFF    10240               // per-warp A strip: 32 rows x 128B = 4 KB (x4 warps)
#define FEAT_OFF (10240 + 16384)     // per-warp feat strip: 512 B (x4 warps)
#define DYN_BYTES (28672 + 1024)

// ---------------- PTX helpers ----------------
__device__ __forceinline__ uint32_t smem_u32(const void* p) {
    uint32_t a;
    asm("{ .reg .u64 t; cvta.to.shared.u64 t, %1; cvt.u32.u64 %0, t; }" : "=r"(a) : "l"(p));
    return a;
}
__device__ __forceinline__ void ldsm_x4(uint32_t* r, uint32_t addr) {
    asm volatile("ldmatrix.sync.aligned.m8n8.x4.shared.b16 {%0,%1,%2,%3}, [%4];"
                 : "=r"(r[0]), "=r"(r[1]), "=r"(r[2]), "=r"(r[3]) : "r"(addr));
}
__device__ __forceinline__ void mma_f16(float* d, const uint32_t* a,
                                        uint32_t b0, uint32_t b1) {
    asm volatile("mma.sync.aligned.m16n8k16.row.col.f32.f16.f16.f32 "
                 "{%0,%1,%2,%3}, {%4,%5,%6,%7}, {%8,%9}, {%0,%1,%2,%3};"
                 : "+f"(d[0]), "+f"(d[1]), "+f"(d[2]), "+f"(d[3])
                 : "r"(a[0]), "r"(a[1]), "r"(a[2]), "r"(a[3]), "r"(b0), "r"(b1));
}
__device__ __forceinline__ void mma_f16_k8(float* d, uint32_t a0, uint32_t a1,
                                           uint32_t b0) {
    asm volatile("mma.sync.aligned.m16n8k8.row.col.f32.f16.f16.f32 "
                 "{%0,%1,%2,%3}, {%4,%5}, {%6}, {%0,%1,%2,%3};"
                 : "+f"(d[0]), "+f"(d[1]), "+f"(d[2]), "+f"(d[3])
                 : "r"(a0), "r"(a1), "r"(b0));
}

// bilinear gather for one point into f[0..2]
__device__ __forceinline__ void interp3(const float* __restrict__ grid,
                                        float px, float py, float* f) {
    float fx = px * 255.0f, fy = py * 255.0f;
    int x0 = (int)fx, y0 = (int)fy;
    float xf = fx - (float)x0, yf = fy - (float)y0;
    int x1 = min(x0 + 1, 255), y1 = min(y0 + 1, 255);
    const float* tl = grid + (y0 * 256 + x0) * 3;
    const float* tr = grid + (y0 * 256 + x1) * 3;
    const float* bl = grid + (y1 * 256 + x0) * 3;
    const float* br = grid + (y1 * 256 + x1) * 3;
#pragma unroll
    for (int c = 0; c < 3; c++) {
        float top = (1.0f - xf) * __ldg(tl + c) + xf * __ldg(tr + c);
        float bot = (1.0f - xf) * __ldg(bl + c) + xf * __ldg(br + c);
        f[c] = (1.0f - yf) * top + yf * bot;
    }
}

__global__ __launch_bounds__(TPB, 5) void mlp_hmma_kernel(
    const float* __restrict__ pos, const float* __restrict__ dir,
    const float* __restrict__ pos_grid, const float* __restrict__ dir_grid,
    const float* __restrict__ W1, const float* __restrict__ b1,
    const float* __restrict__ W2, const float* __restrict__ b2,
    const float* __restrict__ W3, const float* __restrict__ b3,
    float* __restrict__ out, int N, int ntiles)
{
    extern __shared__ char dynsmem[];
    __shared__ __align__(16) float sB1[64];
    __shared__ __align__(16) float sB2[64];
    __shared__ __align__(16) float sW3[64];
    __shared__ float sb3;

    const uint32_t raw  = smem_u32(dynsmem);
    const uint32_t base = (raw + 1023u) & ~1023u;
    char* smem = dynsmem + (base - raw);

    const int t    = threadIdx.x;
    const int wid  = t >> 5;
    const int lane = t & 31;
    const int tg   = lane & 3;      // thread-in-group (cols)
    const int g    = lane >> 2;     // group (rows)

    // ---- one-time staging ----
    // W2 -> fp16 single-rounded, swizzled [n][k] 128B rows
    for (int i = t; i < 4096; i += TPB) {
        __half h = __float2half_rn(W2[i]);
        int n = i >> 6, k = i & 63;
        uint32_t off = (uint32_t)(n * 128) + (uint32_t)((k * 2) ^ ((n & 7) << 4));
        *(__half*)(smem + B2_OFF + off) = h;
    }
    // W1 -> fp16 hi/lo, [n=64][k=8] rows of 16B
    if (t < 64) {
        __half hh[8], hl[8];
#pragma unroll
        for (int i = 0; i < 6; i++) {
            float w = W1[t * 6 + i];
            hh[i] = __float2half_rn(w);
            hl[i] = __float2half_rn(w - __half2float(hh[i]));
        }
        hh[6] = hh[7] = hl[6] = hl[7] = __float2half_rn(0.0f);
        *(uint4*)(smem + W1F_OFF + t * 16)        = *(uint4*)hh;
        *(uint4*)(smem + W1F_OFF + 1024 + t * 16) = *(uint4*)hl;
        sB1[t] = b1[t]; sB2[t] = b2[t]; sW3[t] = W3[t];
    }
    if (t == 0) sb3 = b3[0];
    __syncthreads();

    const uint32_t aStrip   = base + A_OFF + wid * 4096;
    const uint32_t featBase = base + FEAT_OFF + wid * 512;
    const uint32_t w1fBase  = base + W1F_OFF;
    const uint32_t bB2      = base + B2_OFF;

    // per-lane ldmatrix address components
    const int rowA  = lane & 15;            // layer-2 A: row within 16-row tile
    const int khA   = lane >> 4;            // layer-2 A: k-half
    const int matB  = lane >> 3;            // layer-2 B x4 packing
    const int nSub  = matB >> 1;
    const int khB   = matB & 1;
    const int rowB7 = lane & 7;

    const int warp_global = blockIdx.x * 4 + wid;
    const int warp_stride = gridDim.x * 4;

    for (int tile = warp_global; tile < ntiles; tile += warp_stride) {
        const int idx  = tile * 32 + lane;
        const bool live = (idx < N);

        // ---- interp ----
        float feat[6];
        if (live) {
            const float2 p = ((const float2*)pos)[idx];
            const float2 d = ((const float2*)dir)[idx];
            interp3(pos_grid, p.x, p.y, feat + 0);
            interp3(dir_grid, d.x, d.y, feat + 3);
        } else {
#pragma unroll
            for (int i = 0; i < 6; i++) feat[i] = 0.0f;
        }

        __syncwarp();   // prev iter's strip reads complete before overwrite

        // ---- stage feat (fp16, k padded to 8) ----
        {
            __half2 q0 = __floats2half2_rn(feat[0], feat[1]);
            __half2 q1 = __floats2half2_rn(feat[2], feat[3]);
            __half2 q2 = __floats2half2_rn(feat[4], feat[5]);
            uint4 pk = make_uint4(*(uint32_t*)&q0, *(uint32_t*)&q1,
                                  *(uint32_t*)&q2, 0u);
            *(uint4*)(smem + (featBase - base) + lane * 16) = pk;
        }
        __syncwarp();

        // ---- layer-1 fragments ----
        uint32_t fA[4];                         // {mt0.a0, mt0.a1, mt1.a0, mt1.a1}
        ldsm_x4(fA, featBase + lane * 16);
        uint32_t w1h[8], w1l[8];
        ldsm_x4(w1h,     w1fBase + lane * 16);          // hi, nt0-3
        ldsm_x4(w1h + 4, w1fBase + 512 + lane * 16);    // hi, nt4-7
        ldsm_x4(w1l,     w1fBase + 1024 + lane * 16);   // lo, nt0-3
        ldsm_x4(w1l + 4, w1fBase + 1536 + lane * 16);   // lo, nt4-7

        // ---- layer-1 MMA (2-term on W1) + epilogue into A strip ----
        const uint32_t co = (uint32_t)(((8 - 0) & 0) ); // placeholder removed below
#pragma unroll
        for (int nt = 0; nt < 8; nt++) {
            float D0[4] = {0, 0, 0, 0};
            float D1[4] = {0, 0, 0, 0};
            mma_f16_k8(D0, fA[0], fA[1], w1h[nt]);
            mma_f16_k8(D0, fA[0], fA[1], w1l[nt]);
            mma_f16_k8(D1, fA[2], fA[3], w1h[nt]);
            mma_f16_k8(D1, fA[2], fA[3], w1l[nt]);

            int c0 = nt * 8 + 2 * tg;
            float2 bb = *(const float2*)&sB1[c0];
            float v00 = D0[0] + bb.x, v01 = D0[1] + bb.y;
            float v02 = D0[2] + bb.x, v03 = D0[3] + bb.y;
            float v10 = D1[0] + bb.x, v11 = D1[1] + bb.y;
            float v12 = D1[2] + bb.x, v13 = D1[3] + bb.y;
            v00 = fmaxf(v00, LEAKY * v00); v01 = fmaxf(v01, LEAKY * v01);
            v02 = fmaxf(v02, LEAKY * v02); v03 = fmaxf(v03, LEAKY * v03);
            v10 = fmaxf(v10, LEAKY * v10); v11 = fmaxf(v11, LEAKY * v11);
            v12 = fmaxf(v12, LEAKY * v12); v13 = fmaxf(v13, LEAKY * v13);
            __half2 h00 = __floats2half2_rn(v00, v01);   // row g
            __half2 h01 = __floats2half2_rn(v02, v03);   // row g+8
            __half2 h10 = __floats2half2_rn(v10, v11);   // row g+16
            __half2 h11 = __floats2half2_rn(v12, v13);   // row g+24
            // A strip: addr = row*128 + ((nt ^ (row&7))<<4) + 4*tg ; row&7 == g
            uint32_t cOff = (uint32_t)(((nt ^ g) << 4) + 4 * tg);
            char* ap = smem + (aStrip - base) + cOff;
            *(uint32_t*)(ap + g * 128)        = *(uint32_t*)&h00;
            *(uint32_t*)(ap + (g + 8) * 128)  = *(uint32_t*)&h01;
            *(uint32_t*)(ap + (g + 16) * 128) = *(uint32_t*)&h10;
            *(uint32_t*)(ap + (g + 24) * 128) = *(uint32_t*)&h11;
        }
        __syncwarp();

        // ---- layer-2 A fragments: 2 M-tiles x 4 K-tiles ----
        uint32_t Ah[2][4][4];
#pragma unroll
        for (int mt = 0; mt < 2; mt++) {
#pragma unroll
            for (int kt = 0; kt < 4; kt++) {
                int row = mt * 16 + rowA;
                uint32_t off = (uint32_t)(row * 128) +
                               (uint32_t)(((kt * 2 + khA) ^ (row & 7)) << 4);
                ldsm_x4(Ah[mt][kt], aStrip + off);
            }
        }

        // ---- layer-2 GEMM (single fp16 term) + epilogue over 4 n-pairs ----
        float acc0 = 0.0f, acc1 = 0.0f, acc2 = 0.0f, acc3 = 0.0f;
#pragma unroll
        for (int np = 0; np < 4; np++) {
            float D0a[4] = {0, 0, 0, 0};
            float D0b[4] = {0, 0, 0, 0};
            float D1a[4] = {0, 0, 0, 0};
            float D1b[4] = {0, 0, 0, 0};
            const uint32_t rOff = (uint32_t)(((np * 2 + nSub) * 8 + rowB7) * 128);
#pragma unroll
            for (int kt = 0; kt < 4; kt++) {
                uint32_t off = rOff + (uint32_t)(((kt * 2 + khB) ^ rowB7) << 4);
                uint32_t bh[4];
                ldsm_x4(bh, bB2 + off);
                mma_f16(D0a, Ah[0][kt], bh[0], bh[1]);
                mma_f16(D0b, Ah[0][kt], bh[2], bh[3]);
                mma_f16(D1a, Ah[1][kt], bh[0], bh[1]);
                mma_f16(D1b, Ah[1][kt], bh[2], bh[3]);
            }
#pragma unroll
            for (int s = 0; s < 2; s++) {
                const float* D0 = s ? D0b : D0a;
                const float* D1 = s ? D1b : D1a;
                int c0 = (np * 2 + s) * 8 + tg * 2;
                float2 w3 = *(const float2*)&sW3[c0];
                float2 bb = *(const float2*)&sB2[c0];
                float v;
                v = D0[0] + bb.x; v = fmaxf(v, LEAKY * v); acc0 = fmaf(v, w3.x, acc0);
                v = D0[1] + bb.y; v = fmaxf(v, LEAKY * v); acc0 = fmaf(v, w3.y, acc0);
                v = D0[2] + bb.x; v = fmaxf(v, LEAKY * v); acc1 = fmaf(v, w3.x, acc1);
                v = D0[3] + bb.y; v = fmaxf(v, LEAKY * v); acc1 = fmaf(v, w3.y, acc1);
                v = D1[0] + bb.x; v = fmaxf(v, LEAKY * v); acc2 = fmaf(v, w3.x, acc2);
                v = D1[1] + bb.y; v = fmaxf(v, LEAKY * v); acc2 = fmaf(v, w3.y, acc2);
                v = D1[2] + bb.x; v = fmaxf(v, LEAKY * v); acc3 = fmaf(v, w3.x, acc3);
                v = D1[3] + bb.y; v = fmaxf(v, LEAKY * v); acc3 = fmaf(v, w3.y, acc3);
            }
        }

        // ---- reduce over the 4 lanes sharing each row group ----
        acc0 += __shfl_xor_sync(0xFFFFFFFF, acc0, 1);
        acc0 += __shfl_xor_sync(0xFFFFFFFF, acc0, 2);
        acc1 += __shfl_xor_sync(0xFFFFFFFF, acc1, 1);
        acc1 += __shfl_xor_sync(0xFFFFFFFF, acc1, 2);
        acc2 += __shfl_xor_sync(0xFFFFFFFF, acc2, 1);
        acc2 += __shfl_xor_sync(0xFFFFFFFF, acc2, 2);
        acc3 += __shfl_xor_sync(0xFFFFFFFF, acc3, 1);
        acc3 += __shfl_xor_sync(0xFFFFFFFF, acc3, 2);

        if (tg == 0) {
            const int rbase = tile * 32 + g;
            float r0 = acc0 + sb3, r1 = acc1 + sb3, r2 = acc2 + sb3, r3 = acc3 + sb3;
            if (rbase      < N) out[rbase]      = 1.0f / (1.0f + __expf(-r0));
            if (rbase + 8  < N) out[rbase + 8]  = 1.0f / (1.0f + __expf(-r1));
            if (rbase + 16 < N) out[rbase + 16] = 1.0f / (1.0f + __expf(-r2));
            if (rbase + 24 < N) out[rbase + 24] = 1.0f / (1.0f + __expf(-r3));
        }
    }
}

extern "C" void kernel_launch(void* const* d_in, const int* in_sizes, int n_in,
                              void* d_out, int out_size)
{
    const float* pos      = (const float*)d_in[0];
    const float* dir      = (const float*)d_in[1];
    const float* pos_grid = (const float*)d_in[2];
    const float* dir_grid = (const float*)d_in[3];
    const float* W1       = (const float*)d_in[4];
    const float* b1       = (const float*)d_in[5];
    const float* W2       = (const float*)d_in[6];
    const float* b2       = (const float*)d_in[7];
    const float* W3       = (const float*)d_in[8];
    const float* b3       = (const float*)d_in[9];
    float* out            = (float*)d_out;

    const int N = in_sizes[0] / 2;             // pos is (N, 2)
    const int ntiles = (N + 31) / 32;          // 32 points per warp-tile

    cudaFuncSetAttribute(mlp_hmma_kernel,
                         cudaFuncAttributeMaxDynamicSharedMemorySize, DYN_BYTES);

    int grid = 760;                            // 152 SMs x 5 CTAs
    if (grid * 4 > ntiles) grid = (ntiles + 3) / 4;
    mlp_hmma_kernel<<<grid, TPB, DYN_BYTES>>>(pos, dir, pos_grid, dir_grid,
                                              W1, b1, W2, b2, W3, b3,
                                              out, N, ntiles);
}

// round 14
// speedup vs baseline: 5.3673x; 1.1548x over previous
#include <cuda_runtime.h>
#include <cuda_fp16.h>
#include <cstdint>
#include <math.h>

#define TPB    128
#define LEAKY  0.01f

// ---- dynamic smem layout (offsets from 1024-aligned base) ----
#define B2_OFF   0                   // 8 KB: W2 fp16 [n=64][k=64], swizzled 128B rows
#define W1F_OFF  8192                // 2 KB: W1 fp16 [n=64][k=8]; hi @+0, lo @+1024
#define FEAT_OFF 10240               // per-warp feat strip: 512 B (x4 warps) = 2 KB
#define DYN_BYTES (12288 + 1024)

// ---------------- PTX helpers ----------------
__device__ __forceinline__ uint32_t smem_u32(const void* p) {
    uint32_t a;
    asm("{ .reg .u64 t; cvta.to.shared.u64 t, %1; cvt.u32.u64 %0, t; }" : "=r"(a) : "l"(p));
    return a;
}
__device__ __forceinline__ void ldsm_x4(uint32_t* r, uint32_t addr) {
    asm volatile("ldmatrix.sync.aligned.m8n8.x4.shared.b16 {%0,%1,%2,%3}, [%4];"
                 : "=r"(r[0]), "=r"(r[1]), "=r"(r[2]), "=r"(r[3]) : "r"(addr));
}
__device__ __forceinline__ void mma_f16(float* d, const uint32_t* a,
                                        uint32_t b0, uint32_t b1) {
    asm volatile("mma.sync.aligned.m16n8k16.row.col.f32.f16.f16.f32 "
                 "{%0,%1,%2,%3}, {%4,%5,%6,%7}, {%8,%9}, {%0,%1,%2,%3};"
                 : "+f"(d[0]), "+f"(d[1]), "+f"(d[2]), "+f"(d[3])
                 : "r"(a[0]), "r"(a[1]), "r"(a[2]), "r"(a[3]), "r"(b0), "r"(b1));
}
__device__ __forceinline__ void mma_f16_k8(float* d, uint32_t a0, uint32_t a1,
                                           uint32_t b0) {
    asm volatile("mma.sync.aligned.m16n8k8.row.col.f32.f16.f16.f32 "
                 "{%0,%1,%2,%3}, {%4,%5}, {%6}, {%0,%1,%2,%3};"
                 : "+f"(d[0]), "+f"(d[1]), "+f"(d[2]), "+f"(d[3])
                 : "r"(a0), "r"(a1), "r"(b0));
}

// bilinear gather for one point into f[0..2]
__device__ __forceinline__ void interp3(const float* __restrict__ grid,
                                        float px, float py, float* f) {
    float fx = px * 255.0f, fy = py * 255.0f;
    int x0 = (int)fx, y0 = (int)fy;
    float xf = fx - (float)x0, yf = fy - (float)y0;
    int x1 = min(x0 + 1, 255), y1 = min(y0 + 1, 255);
    const float* tl = grid + (y0 * 256 + x0) * 3;
    const float* tr = grid + (y0 * 256 + x1) * 3;
    const float* bl = grid + (y1 * 256 + x0) * 3;
    const float* br = grid + (y1 * 256 + x1) * 3;
#pragma unroll
    for (int c = 0; c < 3; c++) {
        float top = (1.0f - xf) * __ldg(tl + c) + xf * __ldg(tr + c);
        float bot = (1.0f - xf) * __ldg(bl + c) + xf * __ldg(br + c);
        f[c] = (1.0f - yf) * top + yf * bot;
    }
}

__global__ __launch_bounds__(TPB, 5) void mlp_hmma_kernel(
    const float* __restrict__ pos, const float* __restrict__ dir,
    const float* __restrict__ pos_grid, const float* __restrict__ dir_grid,
    const float* __restrict__ W1, const float* __restrict__ b1,
    const float* __restrict__ W2, const float* __restrict__ b2,
    const float* __restrict__ W3, const float* __restrict__ b3,
    float* __restrict__ out, int N, int ntiles)
{
    extern __shared__ char dynsmem[];
    __shared__ __align__(16) float sB1[64];
    __shared__ __align__(16) float sB2[64];
    __shared__ __align__(16) float sW3[64];
    __shared__ float sb3;

    const uint32_t raw  = smem_u32(dynsmem);
    const uint32_t base = (raw + 1023u) & ~1023u;
    char* smem = dynsmem + (base - raw);

    const int t    = threadIdx.x;
    const int wid  = t >> 5;
    const int lane = t & 31;
    const int tg   = lane & 3;      // thread-in-group (cols)
    const int g    = lane >> 2;     // group (rows)

    // ---- one-time staging ----
    // W2 -> fp16 single-rounded, swizzled [n][k] 128B rows
    for (int i = t; i < 4096; i += TPB) {
        __half h = __float2half_rn(W2[i]);
        int n = i >> 6, k = i & 63;
        uint32_t off = (uint32_t)(n * 128) + (uint32_t)((k * 2) ^ ((n & 7) << 4));
        *(__half*)(smem + B2_OFF + off) = h;
    }
    // W1 -> fp16 hi/lo, [n=64][k=8] rows of 16B
    if (t < 64) {
        __half hh[8], hl[8];
#pragma unroll
        for (int i = 0; i < 6; i++) {
            float w = W1[t * 6 + i];
            hh[i] = __float2half_rn(w);
            hl[i] = __float2half_rn(w - __half2float(hh[i]));
        }
        hh[6] = hh[7] = hl[6] = hl[7] = __float2half_rn(0.0f);
        *(uint4*)(smem + W1F_OFF + t * 16)        = *(uint4*)hh;
        *(uint4*)(smem + W1F_OFF + 1024 + t * 16) = *(uint4*)hl;
        sB1[t] = b1[t]; sB2[t] = b2[t]; sW3[t] = W3[t];
    }
    if (t == 0) sb3 = b3[0];
    __syncthreads();

    const uint32_t featBase = base + FEAT_OFF + wid * 512;
    const uint32_t w1fBase  = base + W1F_OFF;
    const uint32_t bB2      = base + B2_OFF;

    // layer-2 B ldmatrix x4 packing:
    // lanes 0-7 -> (n0,kh0), 8-15 -> (n0,kh1), 16-23 -> (n1,kh0), 24-31 -> (n1,kh1)
    const int matB  = lane >> 3;
    const int nSub  = matB >> 1;
    const int khB   = matB & 1;
    const int rowB7 = lane & 7;

    const int warp_global = blockIdx.x * 4 + wid;
    const int warp_stride = gridDim.x * 4;

    for (int tile = warp_global; tile < ntiles; tile += warp_stride) {
        const int idx  = tile * 32 + lane;
        const bool live = (idx < N);

        // ---- interp ----
        float feat[6];
        if (live) {
            const float2 p = ((const float2*)pos)[idx];
            const float2 d = ((const float2*)dir)[idx];
            interp3(pos_grid, p.x, p.y, feat + 0);
            interp3(dir_grid, d.x, d.y, feat + 3);
        } else {
#pragma unroll
            for (int i = 0; i < 6; i++) feat[i] = 0.0f;
        }

        __syncwarp();   // prev iter's feat ldmatrix complete before overwrite

        // ---- stage feat (fp16, k padded to 8) ----
        {
            __half2 q0 = __floats2half2_rn(feat[0], feat[1]);
            __half2 q1 = __floats2half2_rn(feat[2], feat[3]);
            __half2 q2 = __floats2half2_rn(feat[4], feat[5]);
            uint4 pk = make_uint4(*(uint32_t*)&q0, *(uint32_t*)&q1,
                                  *(uint32_t*)&q2, 0u);
            *(uint4*)(smem + (featBase - base) + lane * 16) = pk;
        }
        __syncwarp();

        // ---- layer-1 fragments ----
        uint32_t fA[4];                         // rows 0-15 (0,1), rows 16-31 (2,3)
        ldsm_x4(fA, featBase + lane * 16);
        uint32_t w1h[8], w1l[8];
        ldsm_x4(w1h,     w1fBase + lane * 16);          // hi, nt0-3
        ldsm_x4(w1h + 4, w1fBase + 512 + lane * 16);    // hi, nt4-7
        ldsm_x4(w1l,     w1fBase + 1024 + lane * 16);   // lo, nt0-3
        ldsm_x4(w1l + 4, w1fBase + 1536 + lane * 16);   // lo, nt4-7

        // ---- layer-1 MMA (2-term on W1); epilogue packs DIRECTLY into
        //      layer-2 A fragments (D-frag layout == A-frag layout) ----
        uint32_t Ah[2][4][4];
#pragma unroll
        for (int kt = 0; kt < 4; kt++) {
#pragma unroll
            for (int sub = 0; sub < 2; sub++) {
                const int nt = 2 * kt + sub;
                float D0[4] = {0, 0, 0, 0};
                float D1[4] = {0, 0, 0, 0};
                mma_f16_k8(D0, fA[0], fA[1], w1h[nt]);
                mma_f16_k8(D0, fA[0], fA[1], w1l[nt]);
                mma_f16_k8(D1, fA[2], fA[3], w1h[nt]);
                mma_f16_k8(D1, fA[2], fA[3], w1l[nt]);

                const int c0 = nt * 8 + 2 * tg;
                float2 bb = *(const float2*)&sB1[c0];
                float v00 = D0[0] + bb.x, v01 = D0[1] + bb.y;
                float v02 = D0[2] + bb.x, v03 = D0[3] + bb.y;
                float v10 = D1[0] + bb.x, v11 = D1[1] + bb.y;
                float v12 = D1[2] + bb.x, v13 = D1[3] + bb.y;
                v00 = fmaxf(v00, LEAKY * v00); v01 = fmaxf(v01, LEAKY * v01);
                v02 = fmaxf(v02, LEAKY * v02); v03 = fmaxf(v03, LEAKY * v03);
                v10 = fmaxf(v10, LEAKY * v10); v11 = fmaxf(v11, LEAKY * v11);
                v12 = fmaxf(v12, LEAKY * v12); v13 = fmaxf(v13, LEAKY * v13);
                __half2 p00 = __floats2half2_rn(v00, v01);  // row g,    k-pair
                __half2 p01 = __floats2half2_rn(v02, v03);  // row g+8
                __half2 p10 = __floats2half2_rn(v10, v11);  // row g+16
                __half2 p11 = __floats2half2_rn(v12, v13);  // row g+24
                Ah[0][kt][sub * 2]     = *(uint32_t*)&p00;  // a0/a2
                Ah[0][kt][sub * 2 + 1] = *(uint32_t*)&p01;  // a1/a3
                Ah[1][kt][sub * 2]     = *(uint32_t*)&p10;
                Ah[1][kt][sub * 2 + 1] = *(uint32_t*)&p11;
            }
        }

        // ---- layer-2 GEMM (single fp16 term) + epilogue over 4 n-pairs ----
        float acc0 = 0.0f, acc1 = 0.0f, acc2 = 0.0f, acc3 = 0.0f;
#pragma unroll
        for (int np = 0; np < 4; np++) {
            float D0a[4] = {0, 0, 0, 0};
            float D0b[4] = {0, 0, 0, 0};
            float D1a[4] = {0, 0, 0, 0};
            float D1b[4] = {0, 0, 0, 0};
            const uint32_t rOff = (uint32_t)(((np * 2 + nSub) * 8 + rowB7) * 128);
#pragma unroll
            for (int kt = 0; kt < 4; kt++) {
                uint32_t off = rOff + (uint32_t)(((kt * 2 + khB) ^ rowB7) << 4);
                uint32_t bh[4];
                ldsm_x4(bh, bB2 + off);
                mma_f16(D0a, Ah[0][kt], bh[0], bh[1]);
                mma_f16(D0b, Ah[0][kt], bh[2], bh[3]);
                mma_f16(D1a, Ah[1][kt], bh[0], bh[1]);
                mma_f16(D1b, Ah[1][kt], bh[2], bh[3]);
            }
#pragma unroll
            for (int s = 0; s < 2; s++) {
                const float* D0 = s ? D0b : D0a;
                const float* D1 = s ? D1b : D1a;
                int c0 = (np * 2 + s) * 8 + tg * 2;
                float2 w3 = *(const float2*)&sW3[c0];
                float2 bb = *(const float2*)&sB2[c0];
                float v;
                v = D0[0] + bb.x; v = fmaxf(v, LEAKY * v); acc0 = fmaf(v, w3.x, acc0);
                v = D0[1] + bb.y; v = fmaxf(v, LEAKY * v); acc0 = fmaf(v, w3.y, acc0);
                v = D0[2] + bb.x; v = fmaxf(v, LEAKY * v); acc1 = fmaf(v, w3.x, acc1);
                v = D0[3] + bb.y; v = fmaxf(v, LEAKY * v); acc1 = fmaf(v, w3.y, acc1);
                v = D1[0] + bb.x; v = fmaxf(v, LEAKY * v); acc2 = fmaf(v, w3.x, acc2);
                v = D1[1] + bb.y; v = fmaxf(v, LEAKY * v); acc2 = fmaf(v, w3.y, acc2);
                v = D1[2] + bb.x; v = fmaxf(v, LEAKY * v); acc3 = fmaf(v, w3.x, acc3);
                v = D1[3] + bb.y; v = fmaxf(v, LEAKY * v); acc3 = fmaf(v, w3.y, acc3);
            }
        }

        // ---- reduce over the 4 lanes sharing each row group ----
        acc0 += __shfl_xor_sync(0xFFFFFFFF, acc0, 1);
        acc0 += __shfl_xor_sync(0xFFFFFFFF, acc0, 2);
        acc1 += __shfl_xor_sync(0xFFFFFFFF, acc1, 1);
        acc1 += __shfl_xor_sync(0xFFFFFFFF, acc1, 2);
        acc2 += __shfl_xor_sync(0xFFFFFFFF, acc2, 1);
        acc2 += __shfl_xor_sync(0xFFFFFFFF, acc2, 2);
        acc3 += __shfl_xor_sync(0xFFFFFFFF, acc3, 1);
        acc3 += __shfl_xor_sync(0xFFFFFFFF, acc3, 2);

        if (tg == 0) {
            const int rbase = tile * 32 + g;
            float r0 = acc0 + sb3, r1 = acc1 + sb3, r2 = acc2 + sb3, r3 = acc3 + sb3;
            if (rbase      < N) out[rbase]      = 1.0f / (1.0f + __expf(-r0));
            if (rbase + 8  < N) out[rbase + 8]  = 1.0f / (1.0f + __expf(-r1));
            if (rbase + 16 < N) out[rbase + 16] = 1.0f / (1.0f + __expf(-r2));
            if (rbase + 24 < N) out[rbase + 24] = 1.0f / (1.0f + __expf(-r3));
        }
    }
}

extern "C" void kernel_launch(void* const* d_in, const int* in_sizes, int n_in,
                              void* d_out, int out_size)
{
    const float* pos      = (const float*)d_in[0];
    const float* dir      = (const float*)d_in[1];
    const float* pos_grid = (const float*)d_in[2];
    const float* dir_grid = (const float*)d_in[3];
    const float* W1       = (const float*)d_in[4];
    const float* b1       = (const float*)d_in[5];
    const float* W2       = (const float*)d_in[6];
    const float* b2       = (const float*)d_in[7];
    const float* W3       = (const float*)d_in[8];
    const float* b3       = (const float*)d_in[9];
    float* out            = (float*)d_out;

    const int N = in_sizes[0] / 2;             // pos is (N, 2)
    const int ntiles = (N + 31) / 32;          // 32 points per warp-tile

    cudaFuncSetAttribute(mlp_hmma_kernel,
                         cudaFuncAttributeMaxDynamicSharedMemorySize, DYN_BYTES);

    int grid = 760;                            // 152 SMs x 5 CTAs
    if (grid * 4 > ntiles) grid = (ntiles + 3) / 4;
    mlp_hmma_kernel<<<grid, TPB, DYN_BYTES>>>(pos, dir, pos_grid, dir_grid,
                                              W1, b1, W2, b2, W3, b3,
                                              out, N, ntiles);
}

// round 15
// speedup vs baseline: 6.5787x; 1.2257x over previous
#include <cuda_runtime.h>
#include <cuda_fp16.h>
#include <cstdint>
#include <math.h>

#define TPB    128
#define LEAKY  0.01f

// ---- dynamic smem layout (offsets from 1024-aligned base) ----
#define B2_OFF   0                   // 8 KB: W2 fp16 [n=64][k=64], swizzled 128B rows
#define W1F_OFF  8192                // 2 KB: W1 fp16 [n=64][k=8]; hi @+0, lo @+1024
#define FEAT_OFF 10240               // per-warp feat strip: 512 B (x4 warps) = 2 KB
#define DYN_BYTES (12288 + 1024)

// ---- padded grids: one float4 per cell -> 1 LDG.128 per bilinear corner ----
__device__ __align__(16) float4 g_pos_pad[256 * 256];
__device__ __align__(16) float4 g_dir_pad[256 * 256];

__global__ void pad_grids_kernel(const float* __restrict__ pg,
                                 const float* __restrict__ dg)
{
    int i = blockIdx.x * blockDim.x + threadIdx.x;   // 65536 cells
    g_pos_pad[i] = make_float4(pg[3 * i], pg[3 * i + 1], pg[3 * i + 2], 0.0f);
    g_dir_pad[i] = make_float4(dg[3 * i], dg[3 * i + 1], dg[3 * i + 2], 0.0f);
}

// ---------------- PTX helpers ----------------
__device__ __forceinline__ uint32_t smem_u32(const void* p) {
    uint32_t a;
    asm("{ .reg .u64 t; cvta.to.shared.u64 t, %1; cvt.u32.u64 %0, t; }" : "=r"(a) : "l"(p));
    return a;
}
__device__ __forceinline__ void ldsm_x4(uint32_t* r, uint32_t addr) {
    asm volatile("ldmatrix.sync.aligned.m8n8.x4.shared.b16 {%0,%1,%2,%3}, [%4];"
                 : "=r"(r[0]), "=r"(r[1]), "=r"(r[2]), "=r"(r[3]) : "r"(addr));
}
__device__ __forceinline__ void mma_f16(float* d, const uint32_t* a,
                                        uint32_t b0, uint32_t b1) {
    asm volatile("mma.sync.aligned.m16n8k16.row.col.f32.f16.f16.f32 "
                 "{%0,%1,%2,%3}, {%4,%5,%6,%7}, {%8,%9}, {%0,%1,%2,%3};"
                 : "+f"(d[0]), "+f"(d[1]), "+f"(d[2]), "+f"(d[3])
                 : "r"(a[0]), "r"(a[1]), "r"(a[2]), "r"(a[3]), "r"(b0), "r"(b1));
}
__device__ __forceinline__ void mma_f16_k8(float* d, uint32_t a0, uint32_t a1,
                                           uint32_t b0) {
    asm volatile("mma.sync.aligned.m16n8k8.row.col.f32.f16.f16.f32 "
                 "{%0,%1,%2,%3}, {%4,%5}, {%6}, {%0,%1,%2,%3};"
                 : "+f"(d[0]), "+f"(d[1]), "+f"(d[2]), "+f"(d[3])
                 : "r"(a0), "r"(a1), "r"(b0));
}

// bilinear gather from padded float4 grid (1 LDG.128 per corner)
__device__ __forceinline__ void interp3_p(const float4* __restrict__ grid,
                                          float px, float py, float* f) {
    float fx = px * 255.0f, fy = py * 255.0f;
    int x0 = (int)fx, y0 = (int)fy;
    float xf = fx - (float)x0, yf = fy - (float)y0;
    int x1 = min(x0 + 1, 255), y1 = min(y0 + 1, 255);
    float4 tl = __ldg(&grid[y0 * 256 + x0]);
    float4 tr = __ldg(&grid[y0 * 256 + x1]);
    float4 bl = __ldg(&grid[y1 * 256 + x0]);
    float4 br = __ldg(&grid[y1 * 256 + x1]);
    {
        float top = (1.0f - xf) * tl.x + xf * tr.x;
        float bot = (1.0f - xf) * bl.x + xf * br.x;
        f[0] = (1.0f - yf) * top + yf * bot;
    }
    {
        float top = (1.0f - xf) * tl.y + xf * tr.y;
        float bot = (1.0f - xf) * bl.y + xf * br.y;
        f[1] = (1.0f - yf) * top + yf * bot;
    }
    {
        float top = (1.0f - xf) * tl.z + xf * tr.z;
        float bot = (1.0f - xf) * bl.z + xf * br.z;
        f[2] = (1.0f - yf) * top + yf * bot;
    }
}

__global__ __launch_bounds__(TPB, 5) void mlp_hmma_kernel(
    const float* __restrict__ pos, const float* __restrict__ dir,
    const float* __restrict__ W1, const float* __restrict__ b1,
    const float* __restrict__ W2, const float* __restrict__ b2,
    const float* __restrict__ W3, const float* __restrict__ b3,
    float* __restrict__ out, int N, int ntiles)
{
    extern __shared__ char dynsmem[];
    __shared__ __align__(16) float sB1[64];
    __shared__ __align__(16) float4 sEp[32];   // (b2[2i], b2[2i+1], W3[2i], W3[2i+1])
    __shared__ float sb3;

    const uint32_t raw  = smem_u32(dynsmem);
    const uint32_t base = (raw + 1023u) & ~1023u;
    char* smem = dynsmem + (base - raw);

    const int t    = threadIdx.x;
    const int wid  = t >> 5;
    const int lane = t & 31;
    const int tg   = lane & 3;      // thread-in-group (cols)
    const int g    = lane >> 2;     // group (rows)

    // ---- one-time staging ----
    for (int i = t; i < 4096; i += TPB) {
        __half h = __float2half_rn(W2[i]);
        int n = i >> 6, k = i & 63;
        uint32_t off = (uint32_t)(n * 128) + (uint32_t)((k * 2) ^ ((n & 7) << 4));
        *(__half*)(smem + B2_OFF + off) = h;
    }
    if (t < 64) {
        __half hh[8], hl[8];
#pragma unroll
        for (int i = 0; i < 6; i++) {
            float w = W1[t * 6 + i];
            hh[i] = __float2half_rn(w);
            hl[i] = __float2half_rn(w - __half2float(hh[i]));
        }
        hh[6] = hh[7] = hl[6] = hl[7] = __float2half_rn(0.0f);
        *(uint4*)(smem + W1F_OFF + t * 16)        = *(uint4*)hh;
        *(uint4*)(smem + W1F_OFF + 1024 + t * 16) = *(uint4*)hl;
        sB1[t] = b1[t];
    }
    if (t < 32) sEp[t] = make_float4(b2[2 * t], b2[2 * t + 1],
                                     W3[2 * t], W3[2 * t + 1]);
    if (t == 0) sb3 = b3[0];
    __syncthreads();

    const uint32_t featBase = base + FEAT_OFF + wid * 512;
    const uint32_t w1fBase  = base + W1F_OFF;
    const uint32_t bB2      = base + B2_OFF;

    // layer-2 B ldmatrix x4 packing
    const int matB  = lane >> 3;
    const int nSub  = matB >> 1;
    const int khB   = matB & 1;
    const int rowB7 = lane & 7;

    const int warp_global = blockIdx.x * 4 + wid;
    const int warp_stride = gridDim.x * 4;

    for (int tile = warp_global; tile < ntiles; tile += warp_stride) {
        const int idx  = tile * 32 + lane;
        const bool live = (idx < N);

        // ---- interp (padded float4 grids) ----
        float feat[6];
        if (live) {
            const float2 p = ((const float2*)pos)[idx];
            const float2 d = ((const float2*)dir)[idx];
            interp3_p(g_pos_pad, p.x, p.y, feat + 0);
            interp3_p(g_dir_pad, d.x, d.y, feat + 3);
        } else {
#pragma unroll
            for (int i = 0; i < 6; i++) feat[i] = 0.0f;
        }

        __syncwarp();   // prev iter's feat ldmatrix complete before overwrite

        // ---- stage feat (fp16, k padded to 8) ----
        {
            __half2 q0 = __floats2half2_rn(feat[0], feat[1]);
            __half2 q1 = __floats2half2_rn(feat[2], feat[3]);
            __half2 q2 = __floats2half2_rn(feat[4], feat[5]);
            uint4 pk = make_uint4(*(uint32_t*)&q0, *(uint32_t*)&q1,
                                  *(uint32_t*)&q2, 0u);
            *(uint4*)(smem + (featBase - base) + lane * 16) = pk;
        }
        __syncwarp();

        // ---- layer-1 fragments ----
        uint32_t fA[4];
        ldsm_x4(fA, featBase + lane * 16);
        uint32_t w1h[8], w1l[8];
        ldsm_x4(w1h,     w1fBase + lane * 16);          // hi, nt0-3
        ldsm_x4(w1h + 4, w1fBase + 512 + lane * 16);    // hi, nt4-7
        ldsm_x4(w1l,     w1fBase + 1024 + lane * 16);   // lo, nt0-3
        ldsm_x4(w1l + 4, w1fBase + 1536 + lane * 16);   // lo, nt4-7

        // ---- layer-1 MMA (2-term on W1); epilogue packs DIRECTLY into
        //      layer-2 A fragments (D-frag layout == A-frag layout) ----
        uint32_t Ah[2][4][4];
#pragma unroll
        for (int kt = 0; kt < 4; kt++) {
#pragma unroll
            for (int sub = 0; sub < 2; sub++) {
                const int nt = 2 * kt + sub;
                float D0[4] = {0, 0, 0, 0};
                float D1[4] = {0, 0, 0, 0};
                mma_f16_k8(D0, fA[0], fA[1], w1h[nt]);
                mma_f16_k8(D0, fA[0], fA[1], w1l[nt]);
                mma_f16_k8(D1, fA[2], fA[3], w1h[nt]);
                mma_f16_k8(D1, fA[2], fA[3], w1l[nt]);

                const int c0 = nt * 8 + 2 * tg;
                float2 bb = *(const float2*)&sB1[c0];
                float v00 = D0[0] + bb.x, v01 = D0[1] + bb.y;
                float v02 = D0[2] + bb.x, v03 = D0[3] + bb.y;
                float v10 = D1[0] + bb.x, v11 = D1[1] + bb.y;
                float v12 = D1[2] + bb.x, v13 = D1[3] + bb.y;
                v00 = fmaxf(v00, LEAKY * v00); v01 = fmaxf(v01, LEAKY * v01);
                v02 = fmaxf(v02, LEAKY * v02); v03 = fmaxf(v03, LEAKY * v03);
                v10 = fmaxf(v10, LEAKY * v10); v11 = fmaxf(v11, LEAKY * v11);
                v12 = fmaxf(v12, LEAKY * v12); v13 = fmaxf(v13, LEAKY * v13);
                __half2 p00 = __floats2half2_rn(v00, v01);
                __half2 p01 = __floats2half2_rn(v02, v03);
                __half2 p10 = __floats2half2_rn(v10, v11);
                __half2 p11 = __floats2half2_rn(v12, v13);
                Ah[0][kt][sub * 2]     = *(uint32_t*)&p00;
                Ah[0][kt][sub * 2 + 1] = *(uint32_t*)&p01;
                Ah[1][kt][sub * 2]     = *(uint32_t*)&p10;
                Ah[1][kt][sub * 2 + 1] = *(uint32_t*)&p11;
            }
        }

        // ---- layer-2 GEMM (single fp16 term) + epilogue over 4 n-pairs ----
        float acc0 = 0.0f, acc1 = 0.0f, acc2 = 0.0f, acc3 = 0.0f;
#pragma unroll
        for (int np = 0; np < 4; np++) {
            float D0a[4] = {0, 0, 0, 0};
            float D0b[4] = {0, 0, 0, 0};
            float D1a[4] = {0, 0, 0, 0};
            float D1b[4] = {0, 0, 0, 0};
            const uint32_t rOff = (uint32_t)(((np * 2 + nSub) * 8 + rowB7) * 128);
#pragma unroll
            for (int kt = 0; kt < 4; kt++) {
                uint32_t off = rOff + (uint32_t)(((kt * 2 + khB) ^ rowB7) << 4);
                uint32_t bh[4];
                ldsm_x4(bh, bB2 + off);
                mma_f16(D0a, Ah[0][kt], bh[0], bh[1]);
                mma_f16(D0b, Ah[0][kt], bh[2], bh[3]);
                mma_f16(D1a, Ah[1][kt], bh[0], bh[1]);
                mma_f16(D1b, Ah[1][kt], bh[2], bh[3]);
            }
#pragma unroll
            for (int s = 0; s < 2; s++) {
                const float* D0 = s ? D0b : D0a;
                const float* D1 = s ? D1b : D1a;
                int eIdx = (np * 2 + s) * 4 + tg;      // (c0)/2
                float4 e = sEp[eIdx];                  // b2 pair, W3 pair
                float v;
                v = D0[0] + e.x; v = fmaxf(v, LEAKY * v); acc0 = fmaf(v, e.z, acc0);
                v = D0[1] + e.y; v = fmaxf(v, LEAKY * v); acc0 = fmaf(v, e.w, acc0);
                v = D0[2] + e.x; v = fmaxf(v, LEAKY * v); acc1 = fmaf(v, e.z, acc1);
                v = D0[3] + e.y; v = fmaxf(v, LEAKY * v); acc1 = fmaf(v, e.w, acc1);
                v = D1[0] + e.x; v = fmaxf(v, LEAKY * v); acc2 = fmaf(v, e.z, acc2);
                v = D1[1] + e.y; v = fmaxf(v, LEAKY * v); acc2 = fmaf(v, e.w, acc2);
                v = D1[2] + e.x; v = fmaxf(v, LEAKY * v); acc3 = fmaf(v, e.z, acc3);
                v = D1[3] + e.y; v = fmaxf(v, LEAKY * v); acc3 = fmaf(v, e.w, acc3);
            }
        }

        // ---- reduce over the 4 lanes sharing each row group ----
        acc0 += __shfl_xor_sync(0xFFFFFFFF, acc0, 1);
        acc0 += __shfl_xor_sync(0xFFFFFFFF, acc0, 2);
        acc1 += __shfl_xor_sync(0xFFFFFFFF, acc1, 1);
        acc1 += __shfl_xor_sync(0xFFFFFFFF, acc1, 2);
        acc2 += __shfl_xor_sync(0xFFFFFFFF, acc2, 1);
        acc2 += __shfl_xor_sync(0xFFFFFFFF, acc2, 2);
        acc3 += __shfl_xor_sync(0xFFFFFFFF, acc3, 1);
        acc3 += __shfl_xor_sync(0xFFFFFFFF, acc3, 2);

        if (tg == 0) {
            const int rbase = tile * 32 + g;
            float r0 = acc0 + sb3, r1 = acc1 + sb3, r2 = acc2 + sb3, r3 = acc3 + sb3;
            if (rbase      < N) out[rbase]      = 1.0f / (1.0f + __expf(-r0));
            if (rbase + 8  < N) out[rbase + 8]  = 1.0f / (1.0f + __expf(-r1));
            if (rbase + 16 < N) out[rbase + 16] = 1.0f / (1.0f + __expf(-r2));
            if (rbase + 24 < N) out[rbase + 24] = 1.0f / (1.0f + __expf(-r3));
        }
    }
}

extern "C" void kernel_launch(void* const* d_in, const int* in_sizes, int n_in,
                              void* d_out, int out_size)
{
    const float* pos      = (const float*)d_in[0];
    const float* dir      = (const float*)d_in[1];
    const float* pos_grid = (const float*)d_in[2];
    const float* dir_grid = (const float*)d_in[3];
    const float* W1       = (const float*)d_in[4];
    const float* b1       = (const float*)d_in[5];
    const float* W2       = (const float*)d_in[6];
    const float* b2       = (const float*)d_in[7];
    const float* W3       = (const float*)d_in[8];
    const float* b3       = (const float*)d_in[9];
    float* out            = (float*)d_out;

    const int N = in_sizes[0] / 2;             // pos is (N, 2)
    const int ntiles = (N + 31) / 32;          // 32 points per warp-tile

    // 1) pad grids into float4 cells (stream-ordered before main kernel)
    pad_grids_kernel<<<256, 256>>>(pos_grid, dir_grid);

    // 2) fused MLP
    cudaFuncSetAttribute(mlp_hmma_kernel,
                         cudaFuncAttributeMaxDynamicSharedMemorySize, DYN_BYTES);
    int grid = 760;                            // 152 SMs x 5 CTAs
    if (grid * 4 > ntiles) grid = (ntiles + 3) / 4;
    mlp_hmma_kernel<<<grid, TPB, DYN_BYTES>>>(pos, dir,
                                              W1, b1, W2, b2, W3, b3,
                                              out, N, ntiles);
}

// round 17
// speedup vs baseline: 6.7982x; 1.0334x over previous
#include <cuda_runtime.h>
#include <cuda_fp16.h>
#include <cstdint>
#include <math.h>

#define TPB    128
#define LEAKY  0.01f

// ---- dynamic smem layout (offsets from 1024-aligned base) ----
#define B2_OFF   0                   // 8 KB: W2 fp16 [n=64][k=64], swizzled 128B rows
#define W1F_OFF  8192                // 2 KB: W1 fp16 [n=64][k=8]; hi @+0, lo @+1024
#define FEAT_OFF 10240               // per-warp feat strip: 512 B (x4 warps) = 2 KB
#define DYN_BYTES (12288 + 1024)

// ---- paired-fp16 grids: cell i holds fp16 of cells (y,x) and (y,x+1) ----
// One LDG.128 fetches BOTH horizontal bilinear corners.
__device__ __align__(16) uint4 g_pos_pad[256 * 256];
__device__ __align__(16) uint4 g_dir_pad[256 * 256];

__global__ void pad_grids_kernel(const float* __restrict__ pg,
                                 const float* __restrict__ dg)
{
    int i = blockIdx.x * blockDim.x + threadIdx.x;   // 65536 cells
    int y = i >> 8, x = i & 255;
    int x1 = min(x + 1, 255);
    {
        const float* c0 = pg + (y * 256 + x) * 3;
        const float* c1 = pg + (y * 256 + x1) * 3;
        __half2 w0 = __floats2half2_rn(c0[0], c0[1]);
        __half2 w1 = __floats2half2_rn(c0[2], 0.0f);
        __half2 w2 = __floats2half2_rn(c1[0], c1[1]);
        __half2 w3 = __floats2half2_rn(c1[2], 0.0f);
        g_pos_pad[i] = make_uint4(*(uint32_t*)&w0, *(uint32_t*)&w1,
                                  *(uint32_t*)&w2, *(uint32_t*)&w3);
    }
    {
        const float* c0 = dg + (y * 256 + x) * 3;
        const float* c1 = dg + (y * 256 + x1) * 3;
        __half2 w0 = __floats2half2_rn(c0[0], c0[1]);
        __half2 w1 = __floats2half2_rn(c0[2], 0.0f);
        __half2 w2 = __floats2half2_rn(c1[0], c1[1]);
        __half2 w3 = __floats2half2_rn(c1[2], 0.0f);
        g_dir_pad[i] = make_uint4(*(uint32_t*)&w0, *(uint32_t*)&w1,
                                  *(uint32_t*)&w2, *(uint32_t*)&w3);
    }
}

// ---------------- PTX helpers ----------------
__device__ __forceinline__ uint32_t smem_u32(const void* p) {
    uint32_t a;
    asm("{ .reg .u64 t; cvta.to.shared.u64 t, %1; cvt.u32.u64 %0, t; }" : "=r"(a) : "l"(p));
    return a;
}
__device__ __forceinline__ void ldsm_x4(uint32_t* r, uint32_t addr) {
    asm volatile("ldmatrix.sync.aligned.m8n8.x4.shared.b16 {%0,%1,%2,%3}, [%4];"
                 : "=r"(r[0]), "=r"(r[1]), "=r"(r[2]), "=r"(r[3]) : "r"(addr));
}
__device__ __forceinline__ void mma_f16(float* d, const uint32_t* a,
                                        uint32_t b0, uint32_t b1) {
    asm volatile("mma.sync.aligned.m16n8k16.row.col.f32.f16.f16.f32 "
                 "{%0,%1,%2,%3}, {%4,%5,%6,%7}, {%8,%9}, {%0,%1,%2,%3};"
                 : "+f"(d[0]), "+f"(d[1]), "+f"(d[2]), "+f"(d[3])
                 : "r"(a[0]), "r"(a[1]), "r"(a[2]), "r"(a[3]), "r"(b0), "r"(b1));
}
__device__ __forceinline__ void mma_f16_k8(float* d, uint32_t a0, uint32_t a1,
                                           uint32_t b0) {
    asm volatile("mma.sync.aligned.m16n8k8.row.col.f32.f16.f16.f32 "
                 "{%0,%1,%2,%3}, {%4,%5}, {%6}, {%0,%1,%2,%3};"
                 : "+f"(d[0]), "+f"(d[1]), "+f"(d[2]), "+f"(d[3])
                 : "r"(a0), "r"(a1), "r"(b0));
}

// bilinear gather from paired-fp16 grid: 2 LDG.128 per point per grid
__device__ __forceinline__ void interp3_h(const uint4* __restrict__ grid,
                                          float px, float py, float* f) {
    float fx = px * 255.0f, fy = py * 255.0f;
    int x0 = (int)fx, y0 = (int)fy;
    float xf = fx - (float)x0, yf = fy - (float)y0;
    int y1 = min(y0 + 1, 255);
    uint4 tp = __ldg(&grid[y0 * 256 + x0]);   // tl (3) + tr (3)
    uint4 bt = __ldg(&grid[y1 * 256 + x0]);   // bl (3) + br (3)
    float2 tl01 = __half22float2(*(__half2*)&tp.x);
    float2 tl2  = __half22float2(*(__half2*)&tp.y);
    float2 tr01 = __half22float2(*(__half2*)&tp.z);
    float2 tr2  = __half22float2(*(__half2*)&tp.w);
    float2 bl01 = __half22float2(*(__half2*)&bt.x);
    float2 bl2  = __half22float2(*(__half2*)&bt.y);
    float2 br01 = __half22float2(*(__half2*)&bt.z);
    float2 br2  = __half22float2(*(__half2*)&bt.w);
    float ixf = 1.0f - xf, iyf = 1.0f - yf;
    {
        float top = ixf * tl01.x + xf * tr01.x;
        float bot = ixf * bl01.x + xf * br01.x;
        f[0] = iyf * top + yf * bot;
    }
    {
        float top = ixf * tl01.y + xf * tr01.y;
        float bot = ixf * bl01.y + xf * br01.y;
        f[1] = iyf * top + yf * bot;
    }
    {
        float top = ixf * tl2.x + xf * tr2.x;
        float bot = ixf * bl2.x + xf * br2.x;
        f[2] = iyf * top + yf * bot;
    }
}

__global__ __launch_bounds__(TPB, 5) void mlp_hmma_kernel(
    const float* __restrict__ pos, const float* __restrict__ dir,
    const float* __restrict__ W1, const float* __restrict__ b1,
    const float* __restrict__ W2, const float* __restrict__ b2,
    const float* __restrict__ W3, const float* __restrict__ b3,
    float* __restrict__ out, int N, int ntiles)
{
    extern __shared__ char dynsmem[];
    __shared__ __align__(16) float sB1[64];
    __shared__ __align__(16) float4 sEp[32];   // (b2 pair, W3 pair)
    __shared__ float sb3;

    const uint32_t raw  = smem_u32(dynsmem);
    const uint32_t base = (raw + 1023u) & ~1023u;
    char* smem = dynsmem + (base - raw);

    const int t    = threadIdx.x;
    const int wid  = t >> 5;
    const int lane = t & 31;
    const int tg   = lane & 3;      // thread-in-group (cols)
    const int g    = lane >> 2;     // group (rows)

    // ---- one-time staging ----
    for (int i = t; i < 4096; i += TPB) {
        __half h = __float2half_rn(W2[i]);
        int n = i >> 6, k = i & 63;
        uint32_t off = (uint32_t)(n * 128) + (uint32_t)((k * 2) ^ ((n & 7) << 4));
        *(__half*)(smem + B2_OFF + off) = h;
    }
    if (t < 64) {
        __half hh[8], hl[8];
#pragma unroll
        for (int i = 0; i < 6; i++) {
            float w = W1[t * 6 + i];
            hh[i] = __float2half_rn(w);
            hl[i] = __float2half_rn(w - __half2float(hh[i]));
        }
        hh[6] = hh[7] = hl[6] = hl[7] = __float2half_rn(0.0f);
        *(uint4*)(smem + W1F_OFF + t * 16)        = *(uint4*)hh;
        *(uint4*)(smem + W1F_OFF + 1024 + t * 16) = *(uint4*)hl;
        sB1[t] = b1[t];
    }
    if (t < 32) sEp[t] = make_float4(b2[2 * t], b2[2 * t + 1],
                                     W3[2 * t], W3[2 * t + 1]);
    if (t == 0) sb3 = b3[0];
    __syncthreads();

    const uint32_t featBase = base + FEAT_OFF + wid * 512;
    const uint32_t w1fBase  = base + W1F_OFF;
    const uint32_t bB2      = base + B2_OFF;

    // layer-2 B ldmatrix x4 packing
    const int matB  = lane >> 3;
    const int nSub  = matB >> 1;
    const int khB   = matB & 1;
    const int rowB7 = lane & 7;

    const int warp_global = blockIdx.x * 4 + wid;
    const int warp_stride = gridDim.x * 4;

    for (int tile = warp_global; tile < ntiles; tile += warp_stride) {
        const int idx  = tile * 32 + lane;
        const bool live = (idx < N);

        // ---- interp (paired-fp16 grids: 4 LDG.128 total) ----
        float feat[6];
        if (live) {
            const float2 p = ((const float2*)pos)[idx];
            const float2 d = ((const float2*)dir)[idx];
            interp3_h(g_pos_pad, p.x, p.y, feat + 0);
            interp3_h(g_dir_pad, d.x, d.y, feat + 3);
        } else {
#pragma unroll
            for (int i = 0; i < 6; i++) feat[i] = 0.0f;
        }

        __syncwarp();   // prev iter's feat ldmatrix complete before overwrite

        // ---- stage feat (fp16, k padded to 8) ----
        {
            __half2 q0 = __floats2half2_rn(feat[0], feat[1]);
            __half2 q1 = __floats2half2_rn(feat[2], feat[3]);
            __half2 q2 = __floats2half2_rn(feat[4], feat[5]);
            uint4 pk = make_uint4(*(uint32_t*)&q0, *(uint32_t*)&q1,
                                  *(uint32_t*)&q2, 0u);
            *(uint4*)(smem + (featBase - base) + lane * 16) = pk;
        }
        __syncwarp();

        // ---- layer-1 fragments ----
        uint32_t fA[4];
        ldsm_x4(fA, featBase + lane * 16);
        uint32_t w1h[8], w1l[8];
        ldsm_x4(w1h,     w1fBase + lane * 16);          // hi, nt0-3
        ldsm_x4(w1h + 4, w1fBase + 512 + lane * 16);    // hi, nt4-7
        ldsm_x4(w1l,     w1fBase + 1024 + lane * 16);   // lo, nt0-3
        ldsm_x4(w1l + 4, w1fBase + 1536 + lane * 16);   // lo, nt4-7

        // ---- layer-1 MMA (2-term on W1); epilogue packs DIRECTLY into
        //      layer-2 A fragments (D-frag layout == A-frag layout) ----
        uint32_t Ah[2][4][4];
#pragma unroll
        for (int kt = 0; kt < 4; kt++) {
#pragma unroll
            for (int sub = 0; sub < 2; sub++) {
                const int nt = 2 * kt + sub;
                float D0[4] = {0, 0, 0, 0};
                float D1[4] = {0, 0, 0, 0};
                mma_f16_k8(D0, fA[0], fA[1], w1h[nt]);
                mma_f16_k8(D0, fA[0], fA[1], w1l[nt]);
                mma_f16_k8(D1, fA[2], fA[3], w1h[nt]);
                mma_f16_k8(D1, fA[2], fA[3], w1l[nt]);

                const int c0 = nt * 8 + 2 * tg;
                float2 bb = *(const float2*)&sB1[c0];
                float v00 = D0[0] + bb.x, v01 = D0[1] + bb.y;
                float v02 = D0[2] + bb.x, v03 = D0[3] + bb.y;
                float v10 = D1[0] + bb.x, v11 = D1[1] + bb.y;
                float v12 = D1[2] + bb.x, v13 = D1[3] + bb.y;
                v00 = fmaxf(v00, LEAKY * v00); v01 = fmaxf(v01, LEAKY * v01);
                v02 = fmaxf(v02, LEAKY * v02); v03 = fmaxf(v03, LEAKY * v03);
                v10 = fmaxf(v10, LEAKY * v10); v11 = fmaxf(v11, LEAKY * v11);
                v12 = fmaxf(v12, LEAKY * v12); v13 = fmaxf(v13, LEAKY * v13);
                __half2 p00 = __floats2half2_rn(v00, v01);
                __half2 p01 = __floats2half2_rn(v02, v03);
                __half2 p10 = __floats2half2_rn(v10, v11);
                __half2 p11 = __floats2half2_rn(v12, v13);
                Ah[0][kt][sub * 2]     = *(uint32_t*)&p00;
                Ah[0][kt][sub * 2 + 1] = *(uint32_t*)&p01;
                Ah[1][kt][sub * 2]     = *(uint32_t*)&p10;
                Ah[1][kt][sub * 2 + 1] = *(uint32_t*)&p11;
            }
        }

        // ---- layer-2 GEMM (single fp16 term) + epilogue over 4 n-pairs ----
        float acc0 = 0.0f, acc1 = 0.0f, acc2 = 0.0f, acc3 = 0.0f;
#pragma unroll
        for (int np = 0; np < 4; np++) {
            float D0a[4] = {0, 0, 0, 0};
            float D0b[4] = {0, 0, 0, 0};
            float D1a[4] = {0, 0, 0, 0};
            float D1b[4] = {0, 0, 0, 0};
            const uint32_t rOff = (uint32_t)(((np * 2 + nSub) * 8 + rowB7) * 128);
#pragma unroll
            for (int kt = 0; kt < 4; kt++) {
                uint32_t off = rOff + (uint32_t)(((kt * 2 + khB) ^ rowB7) << 4);
                uint32_t bh[4];
                ldsm_x4(bh, bB2 + off);
                mma_f16(D0a, Ah[0][kt], bh[0], bh[1]);
                mma_f16(D0b, Ah[0][kt], bh[2], bh[3]);
                mma_f16(D1a, Ah[1][kt], bh[0], bh[1]);
                mma_f16(D1b, Ah[1][kt], bh[2], bh[3]);
            }
#pragma unroll
            for (int s = 0; s < 2; s++) {
                const float* D0 = s ? D0b : D0a;
                const float* D1 = s ? D1b : D1a;
                int eIdx = (np * 2 + s) * 4 + tg;
                float4 e = sEp[eIdx];                  // b2 pair, W3 pair
                float v;
                v = D0[0] + e.x; v = fmaxf(v, LEAKY * v); acc0 = fmaf(v, e.z, acc0);
                v = D0[1] + e.y; v = fmaxf(v, LEAKY * v); acc0 = fmaf(v, e.w, acc0);
                v = D0[2] + e.x; v = fmaxf(v, LEAKY * v); acc1 = fmaf(v, e.z, acc1);
                v = D0[3] + e.y; v = fmaxf(v, LEAKY * v); acc1 = fmaf(v, e.w, acc1);
                v = D1[0] + e.x; v = fmaxf(v, LEAKY * v); acc2 = fmaf(v, e.z, acc2);
                v = D1[1] + e.y; v = fmaxf(v, LEAKY * v); acc2 = fmaf(v, e.w, acc2);
                v = D1[2] + e.x; v = fmaxf(v, LEAKY * v); acc3 = fmaf(v, e.z, acc3);
                v = D1[3] + e.y; v = fmaxf(v, LEAKY * v); acc3 = fmaf(v, e.w, acc3);
            }
        }

        // ---- reduce over the 4 lanes sharing each row group ----
        acc0 += __shfl_xor_sync(0xFFFFFFFF, acc0, 1);
        acc0 += __shfl_xor_sync(0xFFFFFFFF, acc0, 2);
        acc1 += __shfl_xor_sync(0xFFFFFFFF, acc1, 1);
        acc1 += __shfl_xor_sync(0xFFFFFFFF, acc1, 2);
        acc2 += __shfl_xor_sync(0xFFFFFFFF, acc2, 1);
        acc2 += __shfl_xor_sync(0xFFFFFFFF, acc2, 2);
        acc3 += __shfl_xor_sync(0xFFFFFFFF, acc3, 1);
        acc3 += __shfl_xor_sync(0xFFFFFFFF, acc3, 2);

        if (tg == 0) {
            const int rbase = tile * 32 + g;
            float r0 = acc0 + sb3, r1 = acc1 + sb3, r2 = acc2 + sb3, r3 = acc3 + sb3;
            if (rbase      < N) out[rbase]      = 1.0f / (1.0f + __expf(-r0));
            if (rbase + 8  < N) out[rbase + 8]  = 1.0f / (1.0f + __expf(-r1));
            if (rbase + 16 < N) out[rbase + 16] = 1.0f / (1.0f + __expf(-r2));
            if (rbase + 24 < N) out[rbase + 24] = 1.0f / (1.0f + __expf(-r3));
        }
    }
}

extern "C" void kernel_launch(void* const* d_in, const int* in_sizes, int n_in,
                              void* d_out, int out_size)
{
    const float* pos      = (const float*)d_in[0];
    const float* dir      = (const float*)d_in[1];
    const float* pos_grid = (const float*)d_in[2];
    const float* dir_grid = (const float*)d_in[3];
    const float* W1       = (const float*)d_in[4];
    const float* b1       = (const float*)d_in[5];
    const float* W2       = (const float*)d_in[6];
    const float* b2       = (const float*)d_in[7];
    const float* W3       = (const float*)d_in[8];
    const float* b3       = (const float*)d_in[9];
    float* out            = (float*)d_out;

    const int N = in_sizes[0] / 2;             // pos is (N, 2)
    const int ntiles = (N + 31) / 32;          // 32 points per warp-tile

    // 1) pad grids into paired-fp16 cells (stream-ordered before main kernel)
    pad_grids_kernel<<<256, 256>>>(pos_grid, dir_grid);

    // 2) fused MLP
    cudaFuncSetAttribute(mlp_hmma_kernel,
                         cudaFuncAttributeMaxDynamicSharedMemorySize, DYN_BYTES);
    int grid = 760;                            // 152 SMs x 5 CTAs
    if (grid * 4 > ntiles) grid = (ntiles + 3) / 4;
    mlp_hmma_kernel<<<grid, TPB, DYN_BYTES>>>(pos, dir,
                                              W1, b1, W2, b2, W3, b3,
                                              out, N, ntiles);
}